// round 1
// baseline (speedup 1.0000x reference)
#include <cuda_runtime.h>
#include <math.h>
#include <stdint.h>

// ---------------- problem constants ----------------
#define NB 4
#define NL 2048
#define ND 1024
#define NH 16
#define NDH 64
#define NW 128
#define NCS 32
#define NNC 128          // total compressed keys (64 cache + 64 block)
#define NNQ 64           // L / CS
#define NCACHE 2048
#define NWINROWS (NW + NL)   // 2176

// ---------------- scratch buffers (device globals; no mallocs allowed) ----------------
__device__ float g_q[NB*NL*ND];          // scaled q (b,l,h*64+d)
__device__ float g_kbp[NB*NL*ND];
__device__ float g_vbp[NB*NL*ND];
__device__ float g_sh[NB*NL*NH];
__device__ float g_shc[NB*NCACHE*NH];
__device__ float g_sch[NB*NH*NNQ*NCS];
__device__ float g_schc[NB*NH*NNQ*NCS];
__device__ float g_hcm[NB*NNQ*ND];
__device__ float g_compk[NB*NNQ*ND];
__device__ float g_compv[NB*NNQ*ND];
__device__ float g_hcmk[NB*NNQ*ND];
__device__ float g_hcmv[NB*NNQ*ND];
__device__ float g_kcomp[NB*NNC*ND];
__device__ float g_vcomp[NB*NNC*ND];
__device__ float g_hwk[NB*NW*ND];
__device__ float g_hwv[NB*NW*ND];
__device__ float g_kwin[NB*NWINROWS*ND];
__device__ float g_vwin[NB*NWINROWS*ND];
__device__ float g_post[NW*ND];
__device__ float g_posc[NNC*ND];
__device__ float g_pcq[(size_t)NB*NH*NL*NNC];
__device__ float g_attn[NB*NL*ND];

// ---------------- generic fp32 SGEMM: C = alpha*(A@B) + bias ----------------
// A is M x K (row-major) with optional batched row remap:
//   phys_row = (r / a_rpb) * a_bstride + a_off + (r % a_rpb)
// B is K x N row-major. K must be a multiple of 8 (always 1024 here).
__global__ void sgemm_kernel(const float* __restrict__ A, const float* __restrict__ Bm,
                             const float* __restrict__ bias, float* __restrict__ C,
                             int M, int N, int K, float alpha,
                             int a_rpb, int a_bstride, int a_off)
{
    __shared__ float As[8][128];
    __shared__ float Bs[8][128];

    const int tid = threadIdx.x;                // 256 threads
    const int row0 = blockIdx.y * 128;
    const int col0 = blockIdx.x * 128;
    const int ty = tid >> 4;                    // 0..15
    const int tx = tid & 15;                    // 0..15

    float acc[8][8];
    #pragma unroll
    for (int i = 0; i < 8; i++)
        #pragma unroll
        for (int j = 0; j < 8; j++) acc[i][j] = 0.f;

    const int a_lr = tid >> 1;                  // 0..127
    const int a_lc = (tid & 1) * 4;             // 0 or 4
    const int b_lr = tid >> 5;                  // 0..7
    const int b_lc = (tid & 31) * 4;            // 0..124

    const int lrow = row0 + a_lr;
    long arow = -1;
    if (lrow < M) arow = (long)(lrow / a_rpb) * a_bstride + a_off + (lrow % a_rpb);

    for (int k0 = 0; k0 < K; k0 += 8) {
        float4 av = make_float4(0.f, 0.f, 0.f, 0.f);
        if (arow >= 0)
            av = *reinterpret_cast<const float4*>(A + arow * K + k0 + a_lc);
        As[a_lc + 0][a_lr] = av.x;
        As[a_lc + 1][a_lr] = av.y;
        As[a_lc + 2][a_lr] = av.z;
        As[a_lc + 3][a_lr] = av.w;

        const int bcol = col0 + b_lc;
        float4 bv = make_float4(0.f, 0.f, 0.f, 0.f);
        if (bcol + 3 < N) {
            bv = *reinterpret_cast<const float4*>(Bm + (long)(k0 + b_lr) * N + bcol);
        } else {
            float t0 = (bcol + 0 < N) ? Bm[(long)(k0 + b_lr) * N + bcol + 0] : 0.f;
            float t1 = (bcol + 1 < N) ? Bm[(long)(k0 + b_lr) * N + bcol + 1] : 0.f;
            float t2 = (bcol + 2 < N) ? Bm[(long)(k0 + b_lr) * N + bcol + 2] : 0.f;
            float t3 = (bcol + 3 < N) ? Bm[(long)(k0 + b_lr) * N + bcol + 3] : 0.f;
            bv = make_float4(t0, t1, t2, t3);
        }
        Bs[b_lr][b_lc + 0] = bv.x;
        Bs[b_lr][b_lc + 1] = bv.y;
        Bs[b_lr][b_lc + 2] = bv.z;
        Bs[b_lr][b_lc + 3] = bv.w;

        __syncthreads();

        #pragma unroll
        for (int kk = 0; kk < 8; kk++) {
            float4 a0 = *reinterpret_cast<const float4*>(&As[kk][ty * 8]);
            float4 a1 = *reinterpret_cast<const float4*>(&As[kk][ty * 8 + 4]);
            float4 b0 = *reinterpret_cast<const float4*>(&Bs[kk][tx * 8]);
            float4 b1 = *reinterpret_cast<const float4*>(&Bs[kk][tx * 8 + 4]);
            float ar[8] = {a0.x, a0.y, a0.z, a0.w, a1.x, a1.y, a1.z, a1.w};
            float br[8] = {b0.x, b0.y, b0.z, b0.w, b1.x, b1.y, b1.z, b1.w};
            #pragma unroll
            for (int i = 0; i < 8; i++)
                #pragma unroll
                for (int j = 0; j < 8; j++)
                    acc[i][j] += ar[i] * br[j];
        }
        __syncthreads();
    }

    #pragma unroll
    for (int i = 0; i < 8; i++) {
        int r = row0 + ty * 8 + i;
        if (r >= M) continue;
        #pragma unroll
        for (int j = 0; j < 8; j++) {
            int cN = col0 + tx * 8 + j;
            if (cN >= N) continue;
            float v = alpha * acc[i][j];
            if (bias) v += bias[cN];
            C[(long)r * N + cN] = v;
        }
    }
}

// ---------------- per-chunk, per-head softmax of raw scores ----------------
// s_in: (B, Lx, 16) row-major. sc_out: (B, H, Lx/32, 32).
__global__ void chunk_softmax_kernel(const float* __restrict__ s_in, float* __restrict__ sc_out,
                                     int Lx)
{
    const int ncx = Lx / NCS;
    const int bc = blockIdx.x;
    const int b = bc / ncx, c = bc % ncx;
    const int h = threadIdx.x >> 5, s = threadIdx.x & 31;

    float v = s_in[(size_t)(b * Lx + c * NCS + s) * NH + h];
    float m = v;
    #pragma unroll
    for (int o = 16; o; o >>= 1) m = fmaxf(m, __shfl_xor_sync(0xffffffffu, m, o));
    float e = __expf(v - m);
    float sum = e;
    #pragma unroll
    for (int o = 16; o; o >>= 1) sum += __shfl_xor_sync(0xffffffffu, sum, o);
    sc_out[((size_t)(b * NH + h) * ncx + c) * NCS + s] = e / sum;
}

// ---------------- compress: out[b,c,h*64+d] = sum_s sc[b,h,c,s] * x[b,c*32+s,h*64+d] ----------------
__global__ void compress_kernel(const float* __restrict__ x, const float* __restrict__ sc,
                                float* __restrict__ out, int Lx)
{
    const int ncx = Lx / NCS;
    const int b = blockIdx.x / ncx, c = blockIdx.x % ncx;
    __shared__ float w[NH][NCS];
    const int tid = threadIdx.x;    // 256
    for (int i = tid; i < NH * NCS; i += 256) {
        int h = i >> 5, s = i & 31;
        w[h][s] = sc[((size_t)(b * NH + h) * ncx + c) * NCS + s];
    }
    __syncthreads();

    const int col = tid * 4;
    const int h = col >> 6;
    float4 acc = make_float4(0.f, 0.f, 0.f, 0.f);
    #pragma unroll 4
    for (int s = 0; s < NCS; s++) {
        float ws = w[h][s];
        float4 xv = *reinterpret_cast<const float4*>(x + (size_t)(b * Lx + c * NCS + s) * ND + col);
        acc.x += ws * xv.x; acc.y += ws * xv.y; acc.z += ws * xv.z; acc.w += ws * xv.w;
    }
    *reinterpret_cast<float4*>(out + (size_t)(b * ncx + c) * ND + col) = acc;
}

// ---------------- row LayerNorm over D=1024 with flexible output row remap ----------------
// out_row = (r / rpb) * out_bstride + out_off + (r % rpb)
__global__ void ln_kernel(const float* __restrict__ in, float* __restrict__ out,
                          const float* __restrict__ g, const float* __restrict__ be,
                          int rpb, int out_bstride, int out_off)
{
    __shared__ float red[32];
    const int r = blockIdx.x;
    const int tid = threadIdx.x;   // 256

    const float* x = in + (size_t)r * ND;
    float4 v = *reinterpret_cast<const float4*>(x + tid * 4);

    float s = v.x + v.y + v.z + v.w;
    #pragma unroll
    for (int o = 16; o; o >>= 1) s += __shfl_xor_sync(0xffffffffu, s, o);
    if ((tid & 31) == 0) red[tid >> 5] = s;
    __syncthreads();
    if (tid < 32) {
        float t = (tid < 8) ? red[tid] : 0.f;
        #pragma unroll
        for (int o = 4; o; o >>= 1) t += __shfl_xor_sync(0xffffffffu, t, o);
        if (tid == 0) red[0] = t;
    }
    __syncthreads();
    float mean = red[0] * (1.f / ND);
    __syncthreads();

    float d0 = v.x - mean, d1 = v.y - mean, d2 = v.z - mean, d3 = v.w - mean;
    float s2 = d0*d0 + d1*d1 + d2*d2 + d3*d3;
    #pragma unroll
    for (int o = 16; o; o >>= 1) s2 += __shfl_xor_sync(0xffffffffu, s2, o);
    if ((tid & 31) == 0) red[tid >> 5] = s2;
    __syncthreads();
    if (tid < 32) {
        float t = (tid < 8) ? red[tid] : 0.f;
        #pragma unroll
        for (int o = 4; o; o >>= 1) t += __shfl_xor_sync(0xffffffffu, t, o);
        if (tid == 0) red[0] = t;
    }
    __syncthreads();
    float rstd = rsqrtf(red[0] * (1.f / ND) + 1e-5f);

    const int orow = (r / rpb) * out_bstride + out_off + (r % rpb);
    const int c = tid * 4;
    float4 ov;
    ov.x = d0 * rstd * g[c + 0] + be[c + 0];
    ov.y = d1 * rstd * g[c + 1] + be[c + 1];
    ov.z = d2 * rstd * g[c + 2] + be[c + 2];
    ov.w = d3 * rstd * g[c + 3] + be[c + 3];
    *reinterpret_cast<float4*>(out + (size_t)orow * ND + c) = ov;
}

// ---------------- rel-shifted positional scores ----------------
// pcq[b,h,l=qc*32+s, c] = q[b, q2*32+s, h, :] . pos_c[c2, h, :]   where
//   f = 64 + qc*128 + c, q2 = f/129, c2 = f%129 (zero if c2==128)
__global__ void pcq_kernel(const float* __restrict__ q, const float* __restrict__ posc,
                           float* __restrict__ pcq)
{
    extern __shared__ float sm[];
    float* pc_s = sm;                    // 128*64
    float* qt   = sm + 128 * 64;         // 64*64

    const int blk = blockIdx.x;
    const int qc = blk & 63;
    const int h  = (blk >> 6) & 15;
    const int b  = blk >> 10;
    const int tid = threadIdx.x;         // 256

    for (int i = tid; i < 128 * 64; i += 256) {
        int crow = i >> 6, d = i & 63;
        pc_s[i] = posc[(size_t)crow * ND + h * NDH + d];
    }
    const int q2_0 = (64 + qc * 128) / 129;
    for (int i = tid; i < 64 * 64; i += 256) {
        int rr = i >> 6, d = i & 63;
        int l = q2_0 * NCS + rr;
        qt[i] = (l < NL) ? q[(size_t)(b * NL + l) * ND + h * NDH + d] : 0.f;
    }
    __syncthreads();

    for (int i = tid; i < NCS * NNC; i += 256) {
        int s = i >> 7, c = i & 127;
        int f = 64 + qc * 128 + c;
        int q2 = f / 129;
        int c2 = f - q2 * 129;
        float val = 0.f;
        if (c2 < 128) {
            const float* qrow = qt + ((q2 - q2_0) * NCS + s) * 64;
            const float* prow = pc_s + c2 * 64;
            #pragma unroll
            for (int d = 0; d < 64; d++) val += qrow[d] * prow[d];
        }
        pcq[((size_t)(b * NH + h) * NL + qc * NCS + s) * NNC + c] = val;
    }
}

// ---------------- fused attention: scores + softmax + AV ----------------
// one block per (b, h, 32-query chunk); 256 threads
#define KBS 65   // padded kbuf row stride
__global__ void attn_kernel(const float* __restrict__ q, const float* __restrict__ kcomp,
                            const float* __restrict__ vcomp, const float* __restrict__ kwin,
                            const float* __restrict__ vwin, const float* __restrict__ post,
                            const float* __restrict__ pcq, const float* __restrict__ rwb,
                            const float* __restrict__ rrb, float* __restrict__ outp)
{
    extern __shared__ float sm[];
    float* qs   = sm;                         // 32*64
    float* sc   = qs + 32 * 64;               // 32*256
    float* kb   = sc + 32 * 256;              // 160*KBS
    float* rwbs = kb + 160 * KBS;             // 64
    float* rrbs = rwbs + 64;                  // 64

    const int tid = threadIdx.x;
    const int blk = blockIdx.x;
    const int qc = blk & 63;
    const int h  = (blk >> 6) & 15;
    const int b  = blk >> 10;
    const int l0 = qc * NCS;

    for (int i = tid; i < 32 * 64; i += 256) {
        int r = i >> 6, d = i & 63;
        qs[i] = q[(size_t)(b * NL + l0 + r) * ND + h * NDH + d];
    }
    if (tid < 64) { rwbs[tid] = rwb[h * NDH + tid]; rrbs[tid] = rrb[h * NDH + tid]; }
    __syncthreads();

    const int ty = tid >> 4, tx = tid & 15;
    const int qi0 = ty * 2;

    // --- compressed-key scores: sc[qi][c], c in [0,128) ---
    for (int ck = 0; ck < 4; ck++) {
        for (int i = tid; i < 32 * 64; i += 256) {
            int r = i >> 6, d = i & 63;
            kb[r * KBS + d] = kcomp[(size_t)(b * NNC + ck * 32 + r) * ND + h * NDH + d];
        }
        __syncthreads();
        const int kj0 = tx * 2;
        float a00 = 0.f, a01 = 0.f, a10 = 0.f, a11 = 0.f;
        #pragma unroll
        for (int d = 0; d < 64; d++) {
            float x0 = qs[qi0 * 64 + d], x1 = qs[qi0 * 64 + 64 + d];
            float y0 = kb[kj0 * KBS + d], y1 = kb[kj0 * KBS + KBS + d];
            a00 += x0 * y0; a01 += x0 * y1; a10 += x1 * y0; a11 += x1 * y1;
        }
        sc[qi0 * 256 + ck * 32 + kj0]         = a00;
        sc[qi0 * 256 + ck * 32 + kj0 + 1]     = a01;
        sc[(qi0 + 1) * 256 + ck * 32 + kj0]   = a10;
        sc[(qi0 + 1) * 256 + ck * 32 + kj0 + 1] = a11;
        __syncthreads();
    }

    // --- positional window term: sc[qi][128+j] = (q+rrb) . pos_t[j] ---
    for (int ck = 0; ck < 4; ck++) {
        for (int i = tid; i < 32 * 64; i += 256) {
            int r = i >> 6, d = i & 63;
            kb[r * KBS + d] = post[(size_t)(ck * 32 + r) * ND + h * NDH + d];
        }
        __syncthreads();
        const int kj0 = tx * 2;
        float a00 = 0.f, a01 = 0.f, a10 = 0.f, a11 = 0.f;
        #pragma unroll
        for (int d = 0; d < 64; d++) {
            float x0 = qs[qi0 * 64 + d] + rrbs[d];
            float x1 = qs[qi0 * 64 + 64 + d] + rrbs[d];
            float y0 = kb[kj0 * KBS + d], y1 = kb[kj0 * KBS + KBS + d];
            a00 += x0 * y0; a01 += x0 * y1; a10 += x1 * y0; a11 += x1 * y1;
        }
        sc[qi0 * 256 + 128 + ck * 32 + kj0]         = a00;
        sc[qi0 * 256 + 128 + ck * 32 + kj0 + 1]     = a01;
        sc[(qi0 + 1) * 256 + 128 + ck * 32 + kj0]   = a10;
        sc[(qi0 + 1) * 256 + 128 + ck * 32 + kj0 + 1] = a11;
        __syncthreads();
    }

    // --- add rel-shift positional + causal chunk mask ---
    for (int i = tid; i < 32 * 128; i += 256) {
        int s_ = i >> 7, c = i & 127;
        float v = sc[s_ * 256 + c] + pcq[((size_t)(b * NH + h) * NL + l0 + s_) * NNC + c];
        if (c >= 64 && (c - 64) >= qc) v = -1e30f;
        sc[s_ * 256 + c] = v;
    }

    // --- banded window scores: sc[qi][128+j] += (q+rwb) . kwin[l0+1+qi+j] ---
    for (int i = tid; i < 160 * 64; i += 256) {
        int r = i >> 6, d = i & 63;
        int idx = l0 + 1 + r;
        kb[r * KBS + d] = (idx < NWINROWS) ? kwin[(size_t)(b * NWINROWS + idx) * ND + h * NDH + d] : 0.f;
    }
    __syncthreads();
    {
        const int j0 = tx * 8;
        float acc0[8], acc1[8];
        #pragma unroll
        for (int jj = 0; jj < 8; jj++) { acc0[jj] = 0.f; acc1[jj] = 0.f; }
        for (int d = 0; d < 64; d++) {
            float x0 = qs[qi0 * 64 + d] + rwbs[d];
            float x1 = qs[qi0 * 64 + 64 + d] + rwbs[d];
            float kv[9];
            #pragma unroll
            for (int r = 0; r < 9; r++) kv[r] = kb[(qi0 + j0 + r) * KBS + d];
            #pragma unroll
            for (int jj = 0; jj < 8; jj++) { acc0[jj] += x0 * kv[jj]; acc1[jj] += x1 * kv[jj + 1]; }
        }
        #pragma unroll
        for (int jj = 0; jj < 8; jj++) {
            sc[qi0 * 256 + 128 + j0 + jj]       += acc0[jj];
            sc[(qi0 + 1) * 256 + 128 + j0 + jj] += acc1[jj];
        }
    }
    __syncthreads();

    // --- softmax over 256 per row ---
    {
        const int w = tid >> 5, lane = tid & 31;
        for (int r = w; r < 32; r += 8) {
            float m = -1e30f;
            for (int c = lane; c < 256; c += 32) m = fmaxf(m, sc[r * 256 + c]);
            #pragma unroll
            for (int o = 16; o; o >>= 1) m = fmaxf(m, __shfl_xor_sync(0xffffffffu, m, o));
            float s = 0.f;
            for (int c = lane; c < 256; c += 32) {
                float e = __expf(sc[r * 256 + c] - m);
                sc[r * 256 + c] = e;
                s += e;
            }
            #pragma unroll
            for (int o = 16; o; o >>= 1) s += __shfl_xor_sync(0xffffffffu, s, o);
            float inv = 1.f / s;
            for (int c = lane; c < 256; c += 32) sc[r * 256 + c] *= inv;
        }
    }
    __syncthreads();

    // --- AV ---
    {
        const int d = tid & 63, qg = tid >> 6;
        float acc[8];
        #pragma unroll
        for (int k = 0; k < 8; k++) acc[k] = 0.f;

        for (int c = 0; c < NNC; c++) {
            float v = vcomp[(size_t)(b * NNC + c) * ND + h * NDH + d];
            #pragma unroll
            for (int k = 0; k < 8; k++) acc[k] += sc[(qg + 4 * k) * 256 + c] * v;
        }
        __syncthreads();
        for (int i = tid; i < 160 * 64; i += 256) {
            int r = i >> 6, dd = i & 63;
            int idx = l0 + 1 + r;
            kb[r * KBS + dd] = (idx < NWINROWS) ? vwin[(size_t)(b * NWINROWS + idx) * ND + h * NDH + dd] : 0.f;
        }
        __syncthreads();
        for (int j = 0; j < NW; j++) {
            #pragma unroll
            for (int k = 0; k < 8; k++) {
                int qi = qg + 4 * k;
                acc[k] += sc[qi * 256 + 128 + j] * kb[(qi + j) * KBS + d];
            }
        }
        #pragma unroll
        for (int k = 0; k < 8; k++)
            outp[(size_t)(b * NL + l0 + qg + 4 * k) * ND + h * NDH + d] = acc[k];
    }
}

// ---------------- host launch ----------------
static inline void gemm(const float* A, const float* Bm, const float* bias, float* C,
                        int M, int N, int K, float alpha,
                        int a_rpb, int a_bstride, int a_off)
{
    dim3 grid((N + 127) / 128, (M + 127) / 128);
    sgemm_kernel<<<grid, 256>>>(A, Bm, bias, C, M, N, K, alpha, a_rpb, a_bstride, a_off);
}

#define GETSYM(p, s) do { void* _t = nullptr; cudaGetSymbolAddress(&_t, s); (p) = (float*)_t; } while (0)

extern "C" void kernel_launch(void* const* d_in, const int* in_sizes, int n_in,
                              void* d_out, int out_size)
{
    const float* h      = (const float*)d_in[0];
    const float* hcache = (const float*)d_in[1];
    const float* key_pe = (const float*)d_in[2];
    const float* poswin = (const float*)d_in[3];
    const float* Wq  = (const float*)d_in[4];
    const float* Wk  = (const float*)d_in[5];
    const float* Wv  = (const float*)d_in[6];
    const float* Wo  = (const float*)d_in[7];
    const float* Wd  = (const float*)d_in[8];
    const float* bd  = (const float*)d_in[9];
    const float* Wr  = (const float*)d_in[10];
    const float* br  = (const float*)d_in[11];
    const float* Wrc = (const float*)d_in[12];
    const float* brc = (const float*)d_in[13];
    const float* rrb = (const float*)d_in[14];   // r_r_bias (1,H,1,DH)
    const float* rwb = (const float*)d_in[15];   // r_w_bias (1,H,1,1,DH)
    const float* g_dp = (const float*)d_in[16];
    const float* b_dp = (const float*)d_in[17];
    const float* g_w  = (const float*)d_in[18];
    const float* b_w  = (const float*)d_in[19];
    float* outp = (float*)d_out;

    float *q, *kbp, *vbp, *sh, *shc, *sch, *schc, *hcm, *compk, *compv;
    float *hcmk, *hcmv, *kcomp, *vcomp, *hwk, *hwv, *kwin, *vwin, *post, *posc, *pcq, *attn;
    GETSYM(q, g_q); GETSYM(kbp, g_kbp); GETSYM(vbp, g_vbp);
    GETSYM(sh, g_sh); GETSYM(shc, g_shc); GETSYM(sch, g_sch); GETSYM(schc, g_schc);
    GETSYM(hcm, g_hcm); GETSYM(compk, g_compk); GETSYM(compv, g_compv);
    GETSYM(hcmk, g_hcmk); GETSYM(hcmv, g_hcmv);
    GETSYM(kcomp, g_kcomp); GETSYM(vcomp, g_vcomp);
    GETSYM(hwk, g_hwk); GETSYM(hwv, g_hwv);
    GETSYM(kwin, g_kwin); GETSYM(vwin, g_vwin);
    GETSYM(post, g_post); GETSYM(posc, g_posc);
    GETSYM(pcq, g_pcq); GETSYM(attn, g_attn);

    const int ATTN_SMEM = (32*64 + 32*256 + 160*KBS + 128) * (int)sizeof(float);
    const int PCQ_SMEM  = (128*64 + 64*64) * (int)sizeof(float);
    cudaFuncSetAttribute(attn_kernel, cudaFuncAttributeMaxDynamicSharedMemorySize, ATTN_SMEM);
    cudaFuncSetAttribute(pcq_kernel,  cudaFuncAttributeMaxDynamicSharedMemorySize, PCQ_SMEM);

    const int M = NB * NL;   // 8192

    // 1. projections of h (q pre-scaled by 1/sqrt(DH) = 0.125)
    gemm(h, Wq, nullptr, q,   M, ND, ND, 0.125f, M, 0, 0);
    gemm(h, Wk, nullptr, kbp, M, ND, ND, 1.f,    M, 0, 0);
    gemm(h, Wv, nullptr, vbp, M, ND, ND, 1.f,    M, 0, 0);

    // 2. chunk scores of h and h_cache
    gemm(h,      Wd, bd, sh,  M, NH, ND, 1.f, M, 0, 0);
    gemm(hcache, Wd, bd, shc, M, NH, ND, 1.f, M, 0, 0);
    chunk_softmax_kernel<<<NB * NNQ, 512>>>(sh,  sch,  NL);
    chunk_softmax_kernel<<<NB * NNQ, 512>>>(shc, schc, NCACHE);

    // 3. compress h_cache (with its own scores), and k_bp/v_bp (with h's scores)
    compress_kernel<<<NB * NNQ, 256>>>(hcache, schc, hcm,   NCACHE);
    compress_kernel<<<NB * NNQ, 256>>>(kbp,    sch,  compk, NL);
    compress_kernel<<<NB * NNQ, 256>>>(vbp,    sch,  compv, NL);

    // 4. cache-side K/V projections + LN into kcomp/vcomp rows [0,64)
    gemm(hcm, Wk, nullptr, hcmk, NB * NNQ, ND, ND, 1.f, NB * NNQ, 0, 0);
    gemm(hcm, Wv, nullptr, hcmv, NB * NNQ, ND, ND, 1.f, NB * NNQ, 0, 0);
    ln_kernel<<<NB * NNQ, 256>>>(hcmk,  kcomp, g_dp, b_dp, NNQ, NNC, 0);
    ln_kernel<<<NB * NNQ, 256>>>(hcmv,  vcomp, g_dp, b_dp, NNQ, NNC, 0);
    // block-side compressed K/V + LN into rows [64,128)
    ln_kernel<<<NB * NNQ, 256>>>(compk, kcomp, g_dp, b_dp, NNQ, NNC, 64);
    ln_kernel<<<NB * NNQ, 256>>>(compv, vcomp, g_dp, b_dp, NNQ, NNC, 64);

    // 5. window K/V: hw = h_cache[:, -W:] (batched A remap), LN(g_win) into kwin/vwin
    gemm(hcache, Wk, nullptr, hwk, NB * NW, ND, ND, 1.f, NW, NCACHE, NCACHE - NW);
    gemm(hcache, Wv, nullptr, hwv, NB * NW, ND, ND, 1.f, NW, NCACHE, NCACHE - NW);
    ln_kernel<<<NB * NW, 256>>>(hwk, kwin, g_w, b_w, NW, NWINROWS, 0);
    ln_kernel<<<NB * NW, 256>>>(hwv, vwin, g_w, b_w, NW, NWINROWS, 0);
    ln_kernel<<<M, 256>>>(kbp, kwin, g_w, b_w, NL, NWINROWS, NW);
    ln_kernel<<<M, 256>>>(vbp, vwin, g_w, b_w, NL, NWINROWS, NW);

    // 6. positional projections
    gemm(poswin, Wr,  br,  post, NW,  ND, ND, 1.f, NW,  0, 0);
    gemm(key_pe, Wrc, brc, posc, NNC, ND, ND, 1.f, NNC, 0, 0);

    // 7. rel-shifted positional scores
    pcq_kernel<<<NB * NH * NNQ, 256, PCQ_SMEM>>>(q, posc, pcq);

    // 8. fused attention
    attn_kernel<<<NB * NH * NNQ, 256, ATTN_SMEM>>>(q, kcomp, vcomp, kwin, vwin,
                                                   post, pcq, rwb, rrb, attn);

    // 9. output projection
    gemm(attn, Wo, nullptr, outp, M, ND, ND, 1.f, M, 0, 0);
}

// round 3
// speedup vs baseline: 1.6785x; 1.6785x over previous
#include <cuda_runtime.h>
#include <cuda_bf16.h>
#include <math.h>
#include <stdint.h>

// ---------------- problem constants ----------------
#define NB 4
#define NL 2048
#define ND 1024
#define NH 16
#define NDH 64
#define NW 128
#define NCS 32
#define NNC 128          // total compressed keys (64 cache + 64 block)
#define NNQ 64           // L / CS
#define NCACHE 2048
#define NWINROWS (NW + NL)   // 2176

// ---------------- scratch buffers (device globals; no mallocs allowed) ----------------
__device__ float g_q[NB*NL*ND];
__device__ float g_kbp[NB*NL*ND];
__device__ float g_vbp[NB*NL*ND];
__device__ float g_sh[NB*NL*NH];
__device__ float g_shc[NB*NCACHE*NH];
__device__ float g_sch[NB*NH*NNQ*NCS];
__device__ float g_schc[NB*NH*NNQ*NCS];
__device__ float g_hcm[NB*NNQ*ND];
__device__ float g_compk[NB*NNQ*ND];
__device__ float g_compv[NB*NNQ*ND];
__device__ float g_hcmk[NB*NNQ*ND];
__device__ float g_hcmv[NB*NNQ*ND];
__device__ float g_kcomp[NB*NNC*ND];
__device__ float g_vcomp[NB*NNC*ND];
__device__ float g_hwk[NB*NW*ND];
__device__ float g_hwv[NB*NW*ND];
__device__ float g_kwin[NB*NWINROWS*ND];
__device__ float g_vwin[NB*NWINROWS*ND];
__device__ float g_post[NW*ND];
__device__ float g_posc[NNC*ND];
__device__ float g_pcq[(size_t)NB*NH*NL*NNC];
__device__ float g_attn[NB*NL*ND];

// bf16 hi/lo split buffers
__device__ __nv_bfloat16 g_ahi[NB*NL*ND];
__device__ __nv_bfloat16 g_alo[NB*NL*ND];
__device__ __nv_bfloat16 g_xhi[512*ND];
__device__ __nv_bfloat16 g_xlo[512*ND];
__device__ __nv_bfloat16 g_wqh[ND*ND], g_wql[ND*ND];
__device__ __nv_bfloat16 g_wkh[ND*ND], g_wkl[ND*ND];
__device__ __nv_bfloat16 g_wvh[ND*ND], g_wvl[ND*ND];
__device__ __nv_bfloat16 g_woh[ND*ND], g_wol[ND*ND];
__device__ __nv_bfloat16 g_wrh[ND*ND], g_wrl[ND*ND];
__device__ __nv_bfloat16 g_wrch[ND*ND], g_wrcl[ND*ND];

// ================= low-level helpers =================
__device__ __forceinline__ uint32_t smem_u32(const void* p) {
    uint32_t a;
    asm("{ .reg .u64 t; cvta.to.shared.u64 t, %1; cvt.u32.u64 %0, t; }" : "=r"(a) : "l"(p));
    return a;
}
__device__ __forceinline__ void ldm_x4(uint32_t& r0, uint32_t& r1, uint32_t& r2, uint32_t& r3,
                                       uint32_t addr) {
    asm volatile("ldmatrix.sync.aligned.m8n8.x4.shared.b16 {%0,%1,%2,%3}, [%4];"
                 : "=r"(r0), "=r"(r1), "=r"(r2), "=r"(r3) : "r"(addr));
}
__device__ __forceinline__ void mma_bf16(float* c, const uint32_t* a, uint32_t b0, uint32_t b1) {
    asm volatile("mma.sync.aligned.m16n8k16.row.col.f32.bf16.bf16.f32 "
                 "{%0,%1,%2,%3}, {%4,%5,%6,%7}, {%8,%9}, {%0,%1,%2,%3};"
                 : "+f"(c[0]), "+f"(c[1]), "+f"(c[2]), "+f"(c[3])
                 : "r"(a[0]), "r"(a[1]), "r"(a[2]), "r"(a[3]), "r"(b0), "r"(b1));
}
#define CP16(dst, src) \
    asm volatile("cp.async.cg.shared.global [%0], [%1], 16;" :: "r"(dst), "l"(src))
#define CP_COMMIT() asm volatile("cp.async.commit_group;" ::: "memory")
#define CP_WAIT1()  asm volatile("cp.async.wait_group 1;" ::: "memory")

// ================= tensor-core GEMM: C[M,N] = alpha*(A @ Bt^T) + bias =================
// A: bf16 hi/lo [M,K] row-major; Bt: bf16 hi/lo [N,K] row-major. fp32 accumulate of
// Ahi*Bhi + Alo*Bhi + Ahi*Blo. M,N multiples of 128, K multiple of 32.
#define TSTR 40                      // smem row stride in bf16 (80 bytes)
#define TILE_B (128 * TSTR * 2)      // 10240 bytes per tile
#define BUF_B  (4 * TILE_B)          // Ahi,Alo,Bhi,Blo = 40960 bytes
#define TG_SMEM_TOTAL (2 * BUF_B)    // double buffered = 81920

__global__ void __launch_bounds__(256, 1)
tgemm_kernel(const __nv_bfloat16* __restrict__ Ahi, const __nv_bfloat16* __restrict__ Alo,
             const __nv_bfloat16* __restrict__ Bhi, const __nv_bfloat16* __restrict__ Blo,
             const float* __restrict__ bias, float* __restrict__ C,
             int M, int N, int K, float alpha)
{
    extern __shared__ char smc[];
    const uint32_t sbase = smem_u32(smc);
    const int tid = threadIdx.x;            // 256
    const int wid = tid >> 5, lane = tid & 31;
    const int row0 = blockIdx.y << 7;
    const int col0 = blockIdx.x << 7;
    const int wm = wid >> 1;                 // 0..3  -> m offset wm*32
    const int wn = wid & 1;                  // 0..1  -> n offset wn*64

    const __nv_bfloat16* srcs[4] = {Ahi, Alo, Bhi, Blo};

    const int nchunks = K >> 5;             // k-chunks of 32

    // prefetch chunk 0 into buffer 0
    {
        #pragma unroll
        for (int it = 0; it < 8; it++) {
            int id = tid + it * 256;          // 0..2047
            int t = id >> 9;                  // tile 0..3
            int j = id & 511;
            int r = j >> 2;                   // 0..127
            int ch = j & 3;                   // 16B chunk
            long grow = (t < 2) ? (long)(row0 + r) : (long)(col0 + r);
            const __nv_bfloat16* src = srcs[t] + grow * K + ch * 8;
            uint32_t dst = sbase + t * TILE_B + r * (TSTR * 2) + ch * 16;
            CP16(dst, src);
        }
        CP_COMMIT();
    }

    float acc[2][8][4];
    #pragma unroll
    for (int mt = 0; mt < 2; mt++)
        #pragma unroll
        for (int nt = 0; nt < 8; nt++)
            #pragma unroll
            for (int f = 0; f < 4; f++) acc[mt][nt][f] = 0.f;

    // per-lane ldmatrix address pieces: lanes 0-15 -> rows, cols+0; 16-31 -> rows, cols+8
    const int lrow = lane & 15;
    const int lcol = (lane >> 4) * 16;       // byte offset for +8 bf16 cols

    for (int kc = 0; kc < nchunks; kc++) {
        const uint32_t buf = sbase + (kc & 1) * BUF_B;
        // prefetch next chunk
        if (kc + 1 < nchunks) {
            const long kb = (long)(kc + 1) << 5;
            const uint32_t nbuf = sbase + ((kc + 1) & 1) * BUF_B;
            #pragma unroll
            for (int it = 0; it < 8; it++) {
                int id = tid + it * 256;
                int t = id >> 9;
                int j = id & 511;
                int r = j >> 2;
                int ch = j & 3;
                long grow = (t < 2) ? (long)(row0 + r) : (long)(col0 + r);
                const __nv_bfloat16* src = srcs[t] + grow * K + kb + ch * 8;
                uint32_t dst = nbuf + t * TILE_B + r * (TSTR * 2) + ch * 16;
                CP16(dst, src);
            }
        }
        CP_COMMIT();
        CP_WAIT1();
        __syncthreads();

        const uint32_t aBase = buf + (wm * 32 + lrow) * (TSTR * 2) + lcol;
        const uint32_t bBase = buf + 2 * TILE_B + (wn * 64 + lrow) * (TSTR * 2) + lcol;

        #pragma unroll
        for (int kk = 0; kk < 2; kk++) {
            const uint32_t ko = kk * 32;     // 16 bf16 cols = 32 bytes
            uint32_t ah[2][4], al[2][4];
            #pragma unroll
            for (int mt = 0; mt < 2; mt++) {
                ldm_x4(ah[mt][0], ah[mt][1], ah[mt][2], ah[mt][3],
                       aBase + mt * 16 * (TSTR * 2) + ko);
                ldm_x4(al[mt][0], al[mt][1], al[mt][2], al[mt][3],
                       aBase + TILE_B + mt * 16 * (TSTR * 2) + ko);
            }
            #pragma unroll
            for (int np = 0; np < 4; np++) {
                uint32_t bh0, bh1, bh2, bh3, bl0, bl1, bl2, bl3;
                ldm_x4(bh0, bh1, bh2, bh3, bBase + np * 16 * (TSTR * 2) + ko);
                ldm_x4(bl0, bl1, bl2, bl3, bBase + TILE_B + np * 16 * (TSTR * 2) + ko);
                #pragma unroll
                for (int mt = 0; mt < 2; mt++) {
                    // n-tile np*2 : frag (r0, r2); n-tile np*2+1 : frag (r1, r3)
                    mma_bf16(acc[mt][np * 2],     ah[mt], bh0, bh2);
                    mma_bf16(acc[mt][np * 2 + 1], ah[mt], bh1, bh3);
                    mma_bf16(acc[mt][np * 2],     al[mt], bh0, bh2);
                    mma_bf16(acc[mt][np * 2 + 1], al[mt], bh1, bh3);
                    mma_bf16(acc[mt][np * 2],     ah[mt], bl0, bl2);
                    mma_bf16(acc[mt][np * 2 + 1], ah[mt], bl1, bl3);
                }
            }
        }
        __syncthreads();
    }

    // epilogue: c frag lane mapping: g = lane>>2, tig = lane&3
    const int g = lane >> 2, tig = lane & 3;
    #pragma unroll
    for (int mt = 0; mt < 2; mt++) {
        const long r0g = row0 + wm * 32 + mt * 16 + g;
        #pragma unroll
        for (int nt = 0; nt < 8; nt++) {
            const int cN = col0 + wn * 64 + nt * 8 + tig * 2;
            float b0 = 0.f, b1 = 0.f;
            if (bias) { b0 = bias[cN]; b1 = bias[cN + 1]; }
            float2 o0 = make_float2(acc[mt][nt][0] * alpha + b0, acc[mt][nt][1] * alpha + b1);
            float2 o1 = make_float2(acc[mt][nt][2] * alpha + b0, acc[mt][nt][3] * alpha + b1);
            *reinterpret_cast<float2*>(C + r0g * N + cN)       = o0;
            *reinterpret_cast<float2*>(C + (r0g + 8) * N + cN) = o1;
        }
    }
}

// ================= fp32 -> bf16 hi/lo split (row remap supported) =================
__global__ void split_kernel(const float* __restrict__ in, __nv_bfloat16* __restrict__ hi,
                             __nv_bfloat16* __restrict__ lo, int rpb, long bstride, long off)
{
    const int r = blockIdx.x;
    const long phys = (long)(r / rpb) * bstride + off + (r % rpb);
    const int c = threadIdx.x * 4;
    float4 v = *reinterpret_cast<const float4*>(in + phys * ND + c);
    __nv_bfloat16 h0 = __float2bfloat16(v.x), h1 = __float2bfloat16(v.y);
    __nv_bfloat16 h2 = __float2bfloat16(v.z), h3 = __float2bfloat16(v.w);
    __nv_bfloat16 l0 = __float2bfloat16(v.x - __bfloat162float(h0));
    __nv_bfloat16 l1 = __float2bfloat16(v.y - __bfloat162float(h1));
    __nv_bfloat16 l2 = __float2bfloat16(v.z - __bfloat162float(h2));
    __nv_bfloat16 l3 = __float2bfloat16(v.w - __bfloat162float(h3));
    __nv_bfloat162 hp0(h0, h1), hp1(h2, h3), lp0(l0, l1), lp1(l2, l3);
    *reinterpret_cast<__nv_bfloat162*>(hi + (long)r * ND + c)     = hp0;
    *reinterpret_cast<__nv_bfloat162*>(hi + (long)r * ND + c + 2) = hp1;
    *reinterpret_cast<__nv_bfloat162*>(lo + (long)r * ND + c)     = lp0;
    *reinterpret_cast<__nv_bfloat162*>(lo + (long)r * ND + c + 2) = lp1;
}

// ================= weight transpose + split: W[K,N] -> WhiT/WloT [N,K] =================
__global__ void wsplit_kernel(const float* __restrict__ W, __nv_bfloat16* __restrict__ hiT,
                              __nv_bfloat16* __restrict__ loT)
{
    __shared__ float t[32][33];
    const int tx = threadIdx.x & 31, ty = threadIdx.x >> 5;   // 32 x 8
    const int k0 = blockIdx.y * 32, n0 = blockIdx.x * 32;
    #pragma unroll
    for (int i = 0; i < 32; i += 8)
        t[ty + i][tx] = W[(long)(k0 + ty + i) * ND + n0 + tx];
    __syncthreads();
    #pragma unroll
    for (int i = 0; i < 32; i += 8) {
        float v = t[tx][ty + i];
        __nv_bfloat16 h = __float2bfloat16(v);
        __nv_bfloat16 l = __float2bfloat16(v - __bfloat162float(h));
        hiT[(long)(n0 + ty + i) * ND + k0 + tx] = h;
        loT[(long)(n0 + ty + i) * ND + k0 + tx] = l;
    }
}

// ================= N=16 GEMV: out[r][c] = x[r,:] @ Wd[:,c] + bd[c] =================
__global__ void gemv16_kernel(const float* __restrict__ x, const float* __restrict__ Wd,
                              const float* __restrict__ bd, float* __restrict__ out)
{
    __shared__ float As[64][65];
    __shared__ float Ws[64][16];
    const int tid = threadIdx.x;             // 256
    const int row0 = blockIdx.x * 64;
    const int col = tid & 15, rg = tid >> 4;
    float acc[4] = {0.f, 0.f, 0.f, 0.f};

    for (int k0 = 0; k0 < ND; k0 += 64) {
        #pragma unroll
        for (int it = 0; it < 16; it++) {
            int i = tid + it * 256;
            int r = i >> 6, c = i & 63;
            As[r][c] = x[(long)(row0 + r) * ND + k0 + c];
        }
        #pragma unroll
        for (int it = 0; it < 4; it++) {
            int i = tid + it * 256;
            int k = i >> 4, c = i & 15;
            Ws[k][c] = Wd[(long)(k0 + k) * NH + c];
        }
        __syncthreads();
        #pragma unroll 8
        for (int k = 0; k < 64; k++) {
            float w = Ws[k][col];
            #pragma unroll
            for (int j = 0; j < 4; j++) acc[j] += As[rg * 4 + j][k] * w;
        }
        __syncthreads();
    }
    #pragma unroll
    for (int j = 0; j < 4; j++)
        out[(long)(row0 + rg * 4 + j) * NH + col] = acc[j] + bd[col];
}

// ---------------- per-chunk, per-head softmax of raw scores ----------------
__global__ void chunk_softmax_kernel(const float* __restrict__ s_in, float* __restrict__ sc_out,
                                     int Lx)
{
    const int ncx = Lx / NCS;
    const int bc = blockIdx.x;
    const int b = bc / ncx, c = bc % ncx;
    const int h = threadIdx.x >> 5, s = threadIdx.x & 31;

    float v = s_in[(size_t)(b * Lx + c * NCS + s) * NH + h];
    float m = v;
    #pragma unroll
    for (int o = 16; o; o >>= 1) m = fmaxf(m, __shfl_xor_sync(0xffffffffu, m, o));
    float e = __expf(v - m);
    float sum = e;
    #pragma unroll
    for (int o = 16; o; o >>= 1) sum += __shfl_xor_sync(0xffffffffu, sum, o);
    sc_out[((size_t)(b * NH + h) * ncx + c) * NCS + s] = e / sum;
}

// ---------------- compress ----------------
__global__ void compress_kernel(const float* __restrict__ x, const float* __restrict__ sc,
                                float* __restrict__ out, int Lx)
{
    const int ncx = Lx / NCS;
    const int b = blockIdx.x / ncx, c = blockIdx.x % ncx;
    __shared__ float w[NH][NCS];
    const int tid = threadIdx.x;
    for (int i = tid; i < NH * NCS; i += 256) {
        int h = i >> 5, s = i & 31;
        w[h][s] = sc[((size_t)(b * NH + h) * ncx + c) * NCS + s];
    }
    __syncthreads();

    const int col = tid * 4;
    const int h = col >> 6;
    float4 acc = make_float4(0.f, 0.f, 0.f, 0.f);
    #pragma unroll 4
    for (int s = 0; s < NCS; s++) {
        float ws = w[h][s];
        float4 xv = *reinterpret_cast<const float4*>(x + (size_t)(b * Lx + c * NCS + s) * ND + col);
        acc.x += ws * xv.x; acc.y += ws * xv.y; acc.z += ws * xv.z; acc.w += ws * xv.w;
    }
    *reinterpret_cast<float4*>(out + (size_t)(b * ncx + c) * ND + col) = acc;
}

// ---------------- row LayerNorm over D=1024 with flexible output row remap ----------------
__global__ void ln_kernel(const float* __restrict__ in, float* __restrict__ out,
                          const float* __restrict__ g, const float* __restrict__ be,
                          int rpb, int out_bstride, int out_off)
{
    __shared__ float red[32];
    const int r = blockIdx.x;
    const int tid = threadIdx.x;

    const float* x = in + (size_t)r * ND;
    float4 v = *reinterpret_cast<const float4*>(x + tid * 4);

    float s = v.x + v.y + v.z + v.w;
    #pragma unroll
    for (int o = 16; o; o >>= 1) s += __shfl_xor_sync(0xffffffffu, s, o);
    if ((tid & 31) == 0) red[tid >> 5] = s;
    __syncthreads();
    if (tid < 32) {
        float t = (tid < 8) ? red[tid] : 0.f;
        #pragma unroll
        for (int o = 4; o; o >>= 1) t += __shfl_xor_sync(0xffffffffu, t, o);
        if (tid == 0) red[0] = t;
    }
    __syncthreads();
    float mean = red[0] * (1.f / ND);
    __syncthreads();

    float d0 = v.x - mean, d1 = v.y - mean, d2 = v.z - mean, d3 = v.w - mean;
    float s2 = d0*d0 + d1*d1 + d2*d2 + d3*d3;
    #pragma unroll
    for (int o = 16; o; o >>= 1) s2 += __shfl_xor_sync(0xffffffffu, s2, o);
    if ((tid & 31) == 0) red[tid >> 5] = s2;
    __syncthreads();
    if (tid < 32) {
        float t = (tid < 8) ? red[tid] : 0.f;
        #pragma unroll
        for (int o = 4; o; o >>= 1) t += __shfl_xor_sync(0xffffffffu, t, o);
        if (tid == 0) red[0] = t;
    }
    __syncthreads();
    float rstd = rsqrtf(red[0] * (1.f / ND) + 1e-5f);

    const int orow = (r / rpb) * out_bstride + out_off + (r % rpb);
    const int c = tid * 4;
    float4 ov;
    ov.x = d0 * rstd * g[c + 0] + be[c + 0];
    ov.y = d1 * rstd * g[c + 1] + be[c + 1];
    ov.z = d2 * rstd * g[c + 2] + be[c + 2];
    ov.w = d3 * rstd * g[c + 3] + be[c + 3];
    *reinterpret_cast<float4*>(out + (size_t)orow * ND + c) = ov;
}

// ---------------- rel-shifted positional scores ----------------
__global__ void pcq_kernel(const float* __restrict__ q, const float* __restrict__ posc,
                           float* __restrict__ pcq)
{
    extern __shared__ float sm[];
    float* pc_s = sm;                    // 128*64
    float* qt   = sm + 128 * 64;         // 64*64

    const int blk = blockIdx.x;
    const int qc = blk & 63;
    const int h  = (blk >> 6) & 15;
    const int b  = blk >> 10;
    const int tid = threadIdx.x;

    for (int i = tid; i < 128 * 64; i += 256) {
        int crow = i >> 6, d = i & 63;
        pc_s[i] = posc[(size_t)crow * ND + h * NDH + d];
    }
    const int q2_0 = (64 + qc * 128) / 129;
    for (int i = tid; i < 64 * 64; i += 256) {
        int rr = i >> 6, d = i & 63;
        int l = q2_0 * NCS + rr;
        qt[i] = (l < NL) ? q[(size_t)(b * NL + l) * ND + h * NDH + d] : 0.f;
    }
    __syncthreads();

    for (int i = tid; i < NCS * NNC; i += 256) {
        int s = i >> 7, c = i & 127;
        int f = 64 + qc * 128 + c;
        int q2 = f / 129;
        int c2 = f - q2 * 129;
        float val = 0.f;
        if (c2 < 128) {
            const float* qrow = qt + ((q2 - q2_0) * NCS + s) * 64;
            const float* prow = pc_s + c2 * 64;
            #pragma unroll
            for (int d = 0; d < 64; d++) val += qrow[d] * prow[d];
        }
        pcq[((size_t)(b * NH + h) * NL + qc * NCS + s) * NNC + c] = val;
    }
}

// ---------------- fused attention: scores + softmax + AV ----------------
#define KBS 65
__global__ void attn_kernel(const float* __restrict__ q, const float* __restrict__ kcomp,
                            const float* __restrict__ vcomp, const float* __restrict__ kwin,
                            const float* __restrict__ vwin, const float* __restrict__ post,
                            const float* __restrict__ pcq, const float* __restrict__ rwb,
                            const float* __restrict__ rrb, float* __restrict__ outp)
{
    extern __shared__ float sm[];
    float* qs   = sm;                         // 32*64
    float* sc   = qs + 32 * 64;               // 32*256
    float* kb   = sc + 32 * 256;              // 160*KBS
    float* rwbs = kb + 160 * KBS;
    float* rrbs = rwbs + 64;

    const int tid = threadIdx.x;
    const int blk = blockIdx.x;
    const int qc = blk & 63;
    const int h  = (blk >> 6) & 15;
    const int b  = blk >> 10;
    const int l0 = qc * NCS;

    for (int i = tid; i < 32 * 64; i += 256) {
        int r = i >> 6, d = i & 63;
        qs[i] = q[(size_t)(b * NL + l0 + r) * ND + h * NDH + d];
    }
    if (tid < 64) { rwbs[tid] = rwb[h * NDH + tid]; rrbs[tid] = rrb[h * NDH + tid]; }
    __syncthreads();

    const int ty = tid >> 4, tx = tid & 15;
    const int qi0 = ty * 2;

    for (int ck = 0; ck < 4; ck++) {
        for (int i = tid; i < 32 * 64; i += 256) {
            int r = i >> 6, d = i & 63;
            kb[r * KBS + d] = kcomp[(size_t)(b * NNC + ck * 32 + r) * ND + h * NDH + d];
        }
        __syncthreads();
        const int kj0 = tx * 2;
        float a00 = 0.f, a01 = 0.f, a10 = 0.f, a11 = 0.f;
        #pragma unroll
        for (int d = 0; d < 64; d++) {
            float x0 = qs[qi0 * 64 + d], x1 = qs[qi0 * 64 + 64 + d];
            float y0 = kb[kj0 * KBS + d], y1 = kb[kj0 * KBS + KBS + d];
            a00 += x0 * y0; a01 += x0 * y1; a10 += x1 * y0; a11 += x1 * y1;
        }
        sc[qi0 * 256 + ck * 32 + kj0]           = a00;
        sc[qi0 * 256 + ck * 32 + kj0 + 1]       = a01;
        sc[(qi0 + 1) * 256 + ck * 32 + kj0]     = a10;
        sc[(qi0 + 1) * 256 + ck * 32 + kj0 + 1] = a11;
        __syncthreads();
    }

    for (int ck = 0; ck < 4; ck++) {
        for (int i = tid; i < 32 * 64; i += 256) {
            int r = i >> 6, d = i & 63;
            kb[r * KBS + d] = post[(size_t)(ck * 32 + r) * ND + h * NDH + d];
        }
        __syncthreads();
        const int kj0 = tx * 2;
        float a00 = 0.f, a01 = 0.f, a10 = 0.f, a11 = 0.f;
        #pragma unroll
        for (int d = 0; d < 64; d++) {
            float x0 = qs[qi0 * 64 + d] + rrbs[d];
            float x1 = qs[qi0 * 64 + 64 + d] + rrbs[d];
            float y0 = kb[kj0 * KBS + d], y1 = kb[kj0 * KBS + KBS + d];
            a00 += x0 * y0; a01 += x0 * y1; a10 += x1 * y0; a11 += x1 * y1;
        }
        sc[qi0 * 256 + 128 + ck * 32 + kj0]           = a00;
        sc[qi0 * 256 + 128 + ck * 32 + kj0 + 1]       = a01;
        sc[(qi0 + 1) * 256 + 128 + ck * 32 + kj0]     = a10;
        sc[(qi0 + 1) * 256 + 128 + ck * 32 + kj0 + 1] = a11;
        __syncthreads();
    }

    for (int i = tid; i < 32 * 128; i += 256) {
        int s_ = i >> 7, c = i & 127;
        float v = sc[s_ * 256 + c] + pcq[((size_t)(b * NH + h) * NL + l0 + s_) * NNC + c];
        if (c >= 64 && (c - 64) >= qc) v = -1e30f;
        sc[s_ * 256 + c] = v;
    }

    for (int i = tid; i < 160 * 64; i += 256) {
        int r = i >> 6, d = i & 63;
        int idx = l0 + 1 + r;
        kb[r * KBS + d] = (idx < NWINROWS) ? kwin[(size_t)(b * NWINROWS + idx) * ND + h * NDH + d] : 0.f;
    }
    __syncthreads();
    {
        const int j0 = tx * 8;
        float acc0[8], acc1[8];
        #pragma unroll
        for (int jj = 0; jj < 8; jj++) { acc0[jj] = 0.f; acc1[jj] = 0.f; }
        for (int d = 0; d < 64; d++) {
            float x0 = qs[qi0 * 64 + d] + rwbs[d];
            float x1 = qs[qi0 * 64 + 64 + d] + rwbs[d];
            float kv[9];
            #pragma unroll
            for (int r = 0; r < 9; r++) kv[r] = kb[(qi0 + j0 + r) * KBS + d];
            #pragma unroll
            for (int jj = 0; jj < 8; jj++) { acc0[jj] += x0 * kv[jj]; acc1[jj] += x1 * kv[jj + 1]; }
        }
        #pragma unroll
        for (int jj = 0; jj < 8; jj++) {
            sc[qi0 * 256 + 128 + j0 + jj]       += acc0[jj];
            sc[(qi0 + 1) * 256 + 128 + j0 + jj] += acc1[jj];
        }
    }
    __syncthreads();

    {
        const int w = tid >> 5, lane = tid & 31;
        for (int r = w; r < 32; r += 8) {
            float m = -1e30f;
            for (int c = lane; c < 256; c += 32) m = fmaxf(m, sc[r * 256 + c]);
            #pragma unroll
            for (int o = 16; o; o >>= 1) m = fmaxf(m, __shfl_xor_sync(0xffffffffu, m, o));
            float s = 0.f;
            for (int c = lane; c < 256; c += 32) {
                float e = __expf(sc[r * 256 + c] - m);
                sc[r * 256 + c] = e;
                s += e;
            }
            #pragma unroll
            for (int o = 16; o; o >>= 1) s += __shfl_xor_sync(0xffffffffu, s, o);
            float inv = 1.f / s;
            for (int c = lane; c < 256; c += 32) sc[r * 256 + c] *= inv;
        }
    }
    __syncthreads();

    {
        const int d = tid & 63, qg = tid >> 6;
        float acc[8];
        #pragma unroll
        for (int k = 0; k < 8; k++) acc[k] = 0.f;

        for (int c = 0; c < NNC; c++) {
            float v = vcomp[(size_t)(b * NNC + c) * ND + h * NDH + d];
            #pragma unroll
            for (int k = 0; k < 8; k++) acc[k] += sc[(qg + 4 * k) * 256 + c] * v;
        }
        __syncthreads();
        for (int i = tid; i < 160 * 64; i += 256) {
            int r = i >> 6, dd = i & 63;
            int idx = l0 + 1 + r;
            kb[r * KBS + dd] = (idx < NWINROWS) ? vwin[(size_t)(b * NWINROWS + idx) * ND + h * NDH + dd] : 0.f;
        }
        __syncthreads();
        for (int j = 0; j < NW; j++) {
            #pragma unroll
            for (int k = 0; k < 8; k++) {
                int qi = qg + 4 * k;
                acc[k] += sc[qi * 256 + 128 + j] * kb[(qi + j) * KBS + d];
            }
        }
        #pragma unroll
        for (int k = 0; k < 8; k++)
            outp[(size_t)(b * NL + l0 + qg + 4 * k) * ND + h * NDH + d] = acc[k];
    }
}

// ---------------- host launch ----------------
#define GETSYM(p, s) do { void* _t = nullptr; cudaGetSymbolAddress(&_t, s); (p) = decltype(p)(_t); } while (0)

static inline void tgemm(const __nv_bfloat16* Ahi, const __nv_bfloat16* Alo,
                         const __nv_bfloat16* Bhi, const __nv_bfloat16* Blo,
                         const float* bias, float* C, int M, int N, int K, float alpha)
{
    dim3 grid(N / 128, M / 128);
    tgemm_kernel<<<grid, 256, TG_SMEM_TOTAL>>>(Ahi, Alo, Bhi, Blo, bias, C, M, N, K, alpha);
}

extern "C" void kernel_launch(void* const* d_in, const int* in_sizes, int n_in,
                              void* d_out, int out_size)
{
    const float* h      = (const float*)d_in[0];
    const float* hcache = (const float*)d_in[1];
    const float* key_pe = (const float*)d_in[2];
    const float* poswin = (const float*)d_in[3];
    const float* Wq  = (const float*)d_in[4];
    const float* Wk  = (const float*)d_in[5];
    const float* Wv  = (const float*)d_in[6];
    const float* Wo  = (const float*)d_in[7];
    const float* Wd  = (const float*)d_in[8];
    const float* bd  = (const float*)d_in[9];
    const float* Wr  = (const float*)d_in[10];
    const float* br  = (const float*)d_in[11];
    const float* Wrc = (const float*)d_in[12];
    const float* brc = (const float*)d_in[13];
    const float* rrb = (const float*)d_in[14];
    const float* rwb = (const float*)d_in[15];
    const float* g_dp = (const float*)d_in[16];
    const float* b_dp = (const float*)d_in[17];
    const float* g_w  = (const float*)d_in[18];
    const float* b_w  = (const float*)d_in[19];
    float* outp = (float*)d_out;

    float *q, *kbp, *vbp, *sh, *shc, *sch, *schc, *hcm, *compk, *compv;
    float *hcmk, *hcmv, *kcomp, *vcomp, *hwk, *hwv, *kwin, *vwin, *post, *posc, *pcq, *attn;
    GETSYM(q, g_q); GETSYM(kbp, g_kbp); GETSYM(vbp, g_vbp);
    GETSYM(sh, g_sh); GETSYM(shc, g_shc); GETSYM(sch, g_sch); GETSYM(schc, g_schc);
    GETSYM(hcm, g_hcm); GETSYM(compk, g_compk); GETSYM(compv, g_compv);
    GETSYM(hcmk, g_hcmk); GETSYM(hcmv, g_hcmv);
    GETSYM(kcomp, g_kcomp); GETSYM(vcomp, g_vcomp);
    GETSYM(hwk, g_hwk); GETSYM(hwv, g_hwv);
    GETSYM(kwin, g_kwin); GETSYM(vwin, g_vwin);
    GETSYM(post, g_post); GETSYM(posc, g_posc);
    GETSYM(pcq, g_pcq); GETSYM(attn, g_attn);

    __nv_bfloat16 *ahi, *alo, *xhi, *xlo;
    __nv_bfloat16 *wqh, *wql, *wkh, *wkl, *wvh, *wvl, *woh, *wol, *wrh, *wrl, *wrch, *wrcl;
    GETSYM(ahi, g_ahi); GETSYM(alo, g_alo); GETSYM(xhi, g_xhi); GETSYM(xlo, g_xlo);
    GETSYM(wqh, g_wqh); GETSYM(wql, g_wql); GETSYM(wkh, g_wkh); GETSYM(wkl, g_wkl);
    GETSYM(wvh, g_wvh); GETSYM(wvl, g_wvl); GETSYM(woh, g_woh); GETSYM(wol, g_wol);
    GETSYM(wrh, g_wrh); GETSYM(wrl, g_wrl); GETSYM(wrch, g_wrch); GETSYM(wrcl, g_wrcl);

    const int ATTN_SMEM = (32*64 + 32*256 + 160*KBS + 128) * (int)sizeof(float);
    const int PCQ_SMEM  = (128*64 + 64*64) * (int)sizeof(float);
    cudaFuncSetAttribute(attn_kernel, cudaFuncAttributeMaxDynamicSharedMemorySize, ATTN_SMEM);
    cudaFuncSetAttribute(pcq_kernel,  cudaFuncAttributeMaxDynamicSharedMemorySize, PCQ_SMEM);
    cudaFuncSetAttribute(tgemm_kernel, cudaFuncAttributeMaxDynamicSharedMemorySize, TG_SMEM_TOTAL);

    const int M = NB * NL;   // 8192

    // 0. weight transpose+split, activation split
    dim3 wg(32, 32);
    wsplit_kernel<<<wg, 256>>>(Wq,  wqh,  wql);
    wsplit_kernel<<<wg, 256>>>(Wk,  wkh,  wkl);
    wsplit_kernel<<<wg, 256>>>(Wv,  wvh,  wvl);
    wsplit_kernel<<<wg, 256>>>(Wo,  woh,  wol);
    wsplit_kernel<<<wg, 256>>>(Wr,  wrh,  wrl);
    wsplit_kernel<<<wg, 256>>>(Wrc, wrch, wrcl);
    split_kernel<<<M, 256>>>(h, ahi, alo, M, 0, 0);

    // 1. projections of h (q pre-scaled by 1/sqrt(DH) = 0.125)
    tgemm(ahi, alo, wqh, wql, nullptr, q,   M, ND, ND, 0.125f);
    tgemm(ahi, alo, wkh, wkl, nullptr, kbp, M, ND, ND, 1.f);
    tgemm(ahi, alo, wvh, wvl, nullptr, vbp, M, ND, ND, 1.f);

    // 2. chunk scores of h and h_cache (N=16 GEMV)
    gemv16_kernel<<<M / 64, 256>>>(h,      Wd, bd, sh);
    gemv16_kernel<<<M / 64, 256>>>(hcache, Wd, bd, shc);
    chunk_softmax_kernel<<<NB * NNQ, 512>>>(sh,  sch,  NL);
    chunk_softmax_kernel<<<NB * NNQ, 512>>>(shc, schc, NCACHE);

    // 3. compress h_cache, k_bp, v_bp
    compress_kernel<<<NB * NNQ, 256>>>(hcache, schc, hcm,   NCACHE);
    compress_kernel<<<NB * NNQ, 256>>>(kbp,    sch,  compk, NL);
    compress_kernel<<<NB * NNQ, 256>>>(vbp,    sch,  compv, NL);

    // 4. cache-side K/V projections + LN into kcomp/vcomp rows [0,64)
    split_kernel<<<NB * NNQ, 256>>>(hcm, xhi, xlo, NB * NNQ, 0, 0);
    tgemm(xhi, xlo, wkh, wkl, nullptr, hcmk, NB * NNQ, ND, ND, 1.f);
    tgemm(xhi, xlo, wvh, wvl, nullptr, hcmv, NB * NNQ, ND, ND, 1.f);
    ln_kernel<<<NB * NNQ, 256>>>(hcmk,  kcomp, g_dp, b_dp, NNQ, NNC, 0);
    ln_kernel<<<NB * NNQ, 256>>>(hcmv,  vcomp, g_dp, b_dp, NNQ, NNC, 0);
    ln_kernel<<<NB * NNQ, 256>>>(compk, kcomp, g_dp, b_dp, NNQ, NNC, 64);
    ln_kernel<<<NB * NNQ, 256>>>(compv, vcomp, g_dp, b_dp, NNQ, NNC, 64);

    // 5. window K/V
    split_kernel<<<NB * NW, 256>>>(hcache, xhi, xlo, NW, NCACHE, NCACHE - NW);
    tgemm(xhi, xlo, wkh, wkl, nullptr, hwk, NB * NW, ND, ND, 1.f);
    tgemm(xhi, xlo, wvh, wvl, nullptr, hwv, NB * NW, ND, ND, 1.f);
    ln_kernel<<<NB * NW, 256>>>(hwk, kwin, g_w, b_w, NW, NWINROWS, 0);
    ln_kernel<<<NB * NW, 256>>>(hwv, vwin, g_w, b_w, NW, NWINROWS, 0);
    ln_kernel<<<M, 256>>>(kbp, kwin, g_w, b_w, NL, NWINROWS, NW);
    ln_kernel<<<M, 256>>>(vbp, vwin, g_w, b_w, NL, NWINROWS, NW);

    // 6. positional projections
    split_kernel<<<NW, 256>>>(poswin, xhi, xlo, NW, 0, 0);
    tgemm(xhi, xlo, wrh, wrl, br, post, NW, ND, ND, 1.f);
    split_kernel<<<NNC, 256>>>(key_pe, xhi, xlo, NNC, 0, 0);
    tgemm(xhi, xlo, wrch, wrcl, brc, posc, NNC, ND, ND, 1.f);

    // 7. rel-shifted positional scores
    pcq_kernel<<<NB * NH * NNQ, 256, PCQ_SMEM>>>(q, posc, pcq);

    // 8. fused attention
    attn_kernel<<<NB * NH * NNQ, 256, ATTN_SMEM>>>(q, kcomp, vcomp, kwin, vwin,
                                                   post, pcq, rwb, rrb, attn);

    // 9. output projection
    split_kernel<<<M, 256>>>(attn, ahi, alo, M, 0, 0);
    tgemm(ahi, alo, woh, wol, nullptr, outp, M, ND, ND, 1.f);
}

// round 4
// speedup vs baseline: 2.6268x; 1.5650x over previous
#include <cuda_runtime.h>
#include <cuda_bf16.h>
#include <math.h>
#include <stdint.h>

// ---------------- problem constants ----------------
#define NB 4
#define NL 2048
#define ND 1024
#define NH 16
#define NDH 64
#define NW 128
#define NCS 32
#define NNC 128          // total compressed keys (64 cache + 64 block)
#define NNQ 64           // L / CS
#define NCACHE 2048
#define NWINROWS (NW + NL)   // 2176

typedef unsigned long long ull;

// ---------------- scratch buffers (device globals; no mallocs allowed) ----------------
__device__ float g_q[NB*NL*ND];
__device__ float g_kbp[NB*NL*ND];
__device__ float g_vbp[NB*NL*ND];
__device__ float g_sh[NB*NL*NH];
__device__ float g_shc[NB*NCACHE*NH];
__device__ float g_sch[NB*NH*NNQ*NCS];
__device__ float g_schc[NB*NH*NNQ*NCS];
__device__ float g_hcm[NB*NNQ*ND];
__device__ float g_compk[NB*NNQ*ND];
__device__ float g_compv[NB*NNQ*ND];
__device__ float g_hcmk[NB*NNQ*ND];
__device__ float g_hcmv[NB*NNQ*ND];
__device__ float g_kcomp[NB*NNC*ND];
__device__ float g_vcomp[NB*NNC*ND];
__device__ float g_hwk[NB*NW*ND];
__device__ float g_hwv[NB*NW*ND];
__device__ float g_kwin[NB*NWINROWS*ND];
__device__ float g_vwin[NB*NWINROWS*ND];
__device__ float g_post[NW*ND];
__device__ float g_posc[NNC*ND];
__device__ float g_pcq[(size_t)NB*NH*NL*NNC];
__device__ float g_attn[NB*NL*ND];

// bf16 hi/lo split buffers
__device__ __nv_bfloat16 g_ahi[NB*NL*ND];
__device__ __nv_bfloat16 g_alo[NB*NL*ND];
__device__ __nv_bfloat16 g_xhi[512*ND];
__device__ __nv_bfloat16 g_xlo[512*ND];
__device__ __nv_bfloat16 g_wqh[ND*ND], g_wql[ND*ND];
__device__ __nv_bfloat16 g_wkh[ND*ND], g_wkl[ND*ND];
__device__ __nv_bfloat16 g_wvh[ND*ND], g_wvl[ND*ND];
__device__ __nv_bfloat16 g_woh[ND*ND], g_wol[ND*ND];
__device__ __nv_bfloat16 g_wrh[ND*ND], g_wrl[ND*ND];
__device__ __nv_bfloat16 g_wrch[ND*ND], g_wrcl[ND*ND];

// ================= low-level helpers =================
__device__ __forceinline__ uint32_t smem_u32(const void* p) {
    uint32_t a;
    asm("{ .reg .u64 t; cvta.to.shared.u64 t, %1; cvt.u32.u64 %0, t; }" : "=r"(a) : "l"(p));
    return a;
}
__device__ __forceinline__ void ldm_x4(uint32_t& r0, uint32_t& r1, uint32_t& r2, uint32_t& r3,
                                       uint32_t addr) {
    asm volatile("ldmatrix.sync.aligned.m8n8.x4.shared.b16 {%0,%1,%2,%3}, [%4];"
                 : "=r"(r0), "=r"(r1), "=r"(r2), "=r"(r3) : "r"(addr));
}
__device__ __forceinline__ void mma_bf16(float* c, const uint32_t* a, uint32_t b0, uint32_t b1) {
    asm volatile("mma.sync.aligned.m16n8k16.row.col.f32.bf16.bf16.f32 "
                 "{%0,%1,%2,%3}, {%4,%5,%6,%7}, {%8,%9}, {%0,%1,%2,%3};"
                 : "+f"(c[0]), "+f"(c[1]), "+f"(c[2]), "+f"(c[3])
                 : "r"(a[0]), "r"(a[1]), "r"(a[2]), "r"(a[3]), "r"(b0), "r"(b1));
}
#define CP16(dst, src) \
    asm volatile("cp.async.cg.shared.global [%0], [%1], 16;" :: "r"(dst), "l"(src))
#define CP_COMMIT() asm volatile("cp.async.commit_group;" ::: "memory")
#define CP_WAIT1()  asm volatile("cp.async.wait_group 1;" ::: "memory")

// packed fp32x2 math (SASS FFMA2 — PTX-only)
__device__ __forceinline__ void fma2(ull& d, ull a, ull b) {
    asm("fma.rn.f32x2 %0, %1, %2, %0;" : "+l"(d) : "l"(a), "l"(b));
}
__device__ __forceinline__ ull add2(ull a, ull b) {
    ull r; asm("add.rn.f32x2 %0, %1, %2;" : "=l"(r) : "l"(a), "l"(b)); return r;
}
__device__ __forceinline__ ull pack2(float x) {
    ull r; asm("mov.b64 %0, {%1, %1};" : "=l"(r) : "f"(x)); return r;
}
__device__ __forceinline__ float fold2(ull v) {
    float lo, hi; asm("mov.b64 {%0, %1}, %2;" : "=f"(lo), "=f"(hi) : "l"(v)); return lo + hi;
}
__device__ __forceinline__ float2 unpack2(ull v) {
    float2 r; asm("mov.b64 {%0, %1}, %2;" : "=f"(r.x), "=f"(r.y) : "l"(v)); return r;
}

// ================= tensor-core GEMM: C[M,N] = alpha*(A @ Bt^T) + bias =================
#define TSTR 40                      // smem row stride in bf16 (80 bytes)
#define TILE_B (128 * TSTR * 2)      // 10240 bytes per tile
#define BUF_B  (4 * TILE_B)          // Ahi,Alo,Bhi,Blo = 40960 bytes
#define TG_SMEM_TOTAL (2 * BUF_B)    // double buffered = 81920

__global__ void __launch_bounds__(256, 1)
tgemm_kernel(const __nv_bfloat16* __restrict__ Ahi, const __nv_bfloat16* __restrict__ Alo,
             const __nv_bfloat16* __restrict__ Bhi, const __nv_bfloat16* __restrict__ Blo,
             const float* __restrict__ bias, float* __restrict__ C,
             int M, int N, int K, float alpha)
{
    extern __shared__ char smc[];
    const uint32_t sbase = smem_u32(smc);
    const int tid = threadIdx.x;            // 256
    const int wid = tid >> 5, lane = tid & 31;
    const int row0 = blockIdx.y << 7;
    const int col0 = blockIdx.x << 7;
    const int wm = wid >> 1;
    const int wn = wid & 1;

    const __nv_bfloat16* srcs[4] = {Ahi, Alo, Bhi, Blo};

    const int nchunks = K >> 5;

    {
        #pragma unroll
        for (int it = 0; it < 8; it++) {
            int id = tid + it * 256;
            int t = id >> 9;
            int j = id & 511;
            int r = j >> 2;
            int ch = j & 3;
            long grow = (t < 2) ? (long)(row0 + r) : (long)(col0 + r);
            const __nv_bfloat16* src = srcs[t] + grow * K + ch * 8;
            uint32_t dst = sbase + t * TILE_B + r * (TSTR * 2) + ch * 16;
            CP16(dst, src);
        }
        CP_COMMIT();
    }

    float acc[2][8][4];
    #pragma unroll
    for (int mt = 0; mt < 2; mt++)
        #pragma unroll
        for (int nt = 0; nt < 8; nt++)
            #pragma unroll
            for (int f = 0; f < 4; f++) acc[mt][nt][f] = 0.f;

    const int lrow = lane & 15;
    const int lcol = (lane >> 4) * 16;

    for (int kc = 0; kc < nchunks; kc++) {
        const uint32_t buf = sbase + (kc & 1) * BUF_B;
        if (kc + 1 < nchunks) {
            const long kb = (long)(kc + 1) << 5;
            const uint32_t nbuf = sbase + ((kc + 1) & 1) * BUF_B;
            #pragma unroll
            for (int it = 0; it < 8; it++) {
                int id = tid + it * 256;
                int t = id >> 9;
                int j = id & 511;
                int r = j >> 2;
                int ch = j & 3;
                long grow = (t < 2) ? (long)(row0 + r) : (long)(col0 + r);
                const __nv_bfloat16* src = srcs[t] + grow * K + kb + ch * 8;
                uint32_t dst = nbuf + t * TILE_B + r * (TSTR * 2) + ch * 16;
                CP16(dst, src);
            }
        }
        CP_COMMIT();
        CP_WAIT1();
        __syncthreads();

        const uint32_t aBase = buf + (wm * 32 + lrow) * (TSTR * 2) + lcol;
        const uint32_t bBase = buf + 2 * TILE_B + (wn * 64 + lrow) * (TSTR * 2) + lcol;

        #pragma unroll
        for (int kk = 0; kk < 2; kk++) {
            const uint32_t ko = kk * 32;
            uint32_t ah[2][4], al[2][4];
            #pragma unroll
            for (int mt = 0; mt < 2; mt++) {
                ldm_x4(ah[mt][0], ah[mt][1], ah[mt][2], ah[mt][3],
                       aBase + mt * 16 * (TSTR * 2) + ko);
                ldm_x4(al[mt][0], al[mt][1], al[mt][2], al[mt][3],
                       aBase + TILE_B + mt * 16 * (TSTR * 2) + ko);
            }
            #pragma unroll
            for (int np = 0; np < 4; np++) {
                uint32_t bh0, bh1, bh2, bh3, bl0, bl1, bl2, bl3;
                ldm_x4(bh0, bh1, bh2, bh3, bBase + np * 16 * (TSTR * 2) + ko);
                ldm_x4(bl0, bl1, bl2, bl3, bBase + TILE_B + np * 16 * (TSTR * 2) + ko);
                #pragma unroll
                for (int mt = 0; mt < 2; mt++) {
                    mma_bf16(acc[mt][np * 2],     ah[mt], bh0, bh2);
                    mma_bf16(acc[mt][np * 2 + 1], ah[mt], bh1, bh3);
                    mma_bf16(acc[mt][np * 2],     al[mt], bh0, bh2);
                    mma_bf16(acc[mt][np * 2 + 1], al[mt], bh1, bh3);
                    mma_bf16(acc[mt][np * 2],     ah[mt], bl0, bl2);
                    mma_bf16(acc[mt][np * 2 + 1], ah[mt], bl1, bl3);
                }
            }
        }
        __syncthreads();
    }

    const int g = lane >> 2, tig = lane & 3;
    #pragma unroll
    for (int mt = 0; mt < 2; mt++) {
        const long r0g = row0 + wm * 32 + mt * 16 + g;
        #pragma unroll
        for (int nt = 0; nt < 8; nt++) {
            const int cN = col0 + wn * 64 + nt * 8 + tig * 2;
            float b0 = 0.f, b1 = 0.f;
            if (bias) { b0 = bias[cN]; b1 = bias[cN + 1]; }
            float2 o0 = make_float2(acc[mt][nt][0] * alpha + b0, acc[mt][nt][1] * alpha + b1);
            float2 o1 = make_float2(acc[mt][nt][2] * alpha + b0, acc[mt][nt][3] * alpha + b1);
            *reinterpret_cast<float2*>(C + r0g * N + cN)       = o0;
            *reinterpret_cast<float2*>(C + (r0g + 8) * N + cN) = o1;
        }
    }
}

// ================= fp32 -> bf16 hi/lo split (row remap supported) =================
__global__ void split_kernel(const float* __restrict__ in, __nv_bfloat16* __restrict__ hi,
                             __nv_bfloat16* __restrict__ lo, int rpb, long bstride, long off)
{
    const int r = blockIdx.x;
    const long phys = (long)(r / rpb) * bstride + off + (r % rpb);
    const int c = threadIdx.x * 4;
    float4 v = *reinterpret_cast<const float4*>(in + phys * ND + c);
    __nv_bfloat16 h0 = __float2bfloat16(v.x), h1 = __float2bfloat16(v.y);
    __nv_bfloat16 h2 = __float2bfloat16(v.z), h3 = __float2bfloat16(v.w);
    __nv_bfloat16 l0 = __float2bfloat16(v.x - __bfloat162float(h0));
    __nv_bfloat16 l1 = __float2bfloat16(v.y - __bfloat162float(h1));
    __nv_bfloat16 l2 = __float2bfloat16(v.z - __bfloat162float(h2));
    __nv_bfloat16 l3 = __float2bfloat16(v.w - __bfloat162float(h3));
    __nv_bfloat162 hp0(h0, h1), hp1(h2, h3), lp0(l0, l1), lp1(l2, l3);
    *reinterpret_cast<__nv_bfloat162*>(hi + (long)r * ND + c)     = hp0;
    *reinterpret_cast<__nv_bfloat162*>(hi + (long)r * ND + c + 2) = hp1;
    *reinterpret_cast<__nv_bfloat162*>(lo + (long)r * ND + c)     = lp0;
    *reinterpret_cast<__nv_bfloat162*>(lo + (long)r * ND + c + 2) = lp1;
}

// ================= weight transpose + split =================
__global__ void wsplit_kernel(const float* __restrict__ W, __nv_bfloat16* __restrict__ hiT,
                              __nv_bfloat16* __restrict__ loT)
{
    __shared__ float t[32][33];
    const int tx = threadIdx.x & 31, ty = threadIdx.x >> 5;
    const int k0 = blockIdx.y * 32, n0 = blockIdx.x * 32;
    #pragma unroll
    for (int i = 0; i < 32; i += 8)
        t[ty + i][tx] = W[(long)(k0 + ty + i) * ND + n0 + tx];
    __syncthreads();
    #pragma unroll
    for (int i = 0; i < 32; i += 8) {
        float v = t[tx][ty + i];
        __nv_bfloat16 h = __float2bfloat16(v);
        __nv_bfloat16 l = __float2bfloat16(v - __bfloat162float(h));
        hiT[(long)(n0 + ty + i) * ND + k0 + tx] = h;
        loT[(long)(n0 + ty + i) * ND + k0 + tx] = l;
    }
}

// ================= N=16 GEMV =================
__global__ void gemv16_kernel(const float* __restrict__ x, const float* __restrict__ Wd,
                              const float* __restrict__ bd, float* __restrict__ out)
{
    __shared__ float As[64][65];
    __shared__ float Ws[64][16];
    const int tid = threadIdx.x;
    const int row0 = blockIdx.x * 64;
    const int col = tid & 15, rg = tid >> 4;
    float acc[4] = {0.f, 0.f, 0.f, 0.f};

    for (int k0 = 0; k0 < ND; k0 += 64) {
        #pragma unroll
        for (int it = 0; it < 16; it++) {
            int i = tid + it * 256;
            int r = i >> 6, c = i & 63;
            As[r][c] = x[(long)(row0 + r) * ND + k0 + c];
        }
        #pragma unroll
        for (int it = 0; it < 4; it++) {
            int i = tid + it * 256;
            int k = i >> 4, c = i & 15;
            Ws[k][c] = Wd[(long)(k0 + k) * NH + c];
        }
        __syncthreads();
        #pragma unroll 8
        for (int k = 0; k < 64; k++) {
            float w = Ws[k][col];
            #pragma unroll
            for (int j = 0; j < 4; j++) acc[j] += As[rg * 4 + j][k] * w;
        }
        __syncthreads();
    }
    #pragma unroll
    for (int j = 0; j < 4; j++)
        out[(long)(row0 + rg * 4 + j) * NH + col] = acc[j] + bd[col];
}

// ---------------- per-chunk, per-head softmax of raw scores ----------------
__global__ void chunk_softmax_kernel(const float* __restrict__ s_in, float* __restrict__ sc_out,
                                     int Lx)
{
    const int ncx = Lx / NCS;
    const int bc = blockIdx.x;
    const int b = bc / ncx, c = bc % ncx;
    const int h = threadIdx.x >> 5, s = threadIdx.x & 31;

    float v = s_in[(size_t)(b * Lx + c * NCS + s) * NH + h];
    float m = v;
    #pragma unroll
    for (int o = 16; o; o >>= 1) m = fmaxf(m, __shfl_xor_sync(0xffffffffu, m, o));
    float e = __expf(v - m);
    float sum = e;
    #pragma unroll
    for (int o = 16; o; o >>= 1) sum += __shfl_xor_sync(0xffffffffu, sum, o);
    sc_out[((size_t)(b * NH + h) * ncx + c) * NCS + s] = e / sum;
}

// ---------------- compress ----------------
__global__ void compress_kernel(const float* __restrict__ x, const float* __restrict__ sc,
                                float* __restrict__ out, int Lx)
{
    const int ncx = Lx / NCS;
    const int b = blockIdx.x / ncx, c = blockIdx.x % ncx;
    __shared__ float w[NH][NCS];
    const int tid = threadIdx.x;
    for (int i = tid; i < NH * NCS; i += 256) {
        int h = i >> 5, s = i & 31;
        w[h][s] = sc[((size_t)(b * NH + h) * ncx + c) * NCS + s];
    }
    __syncthreads();

    const int col = tid * 4;
    const int h = col >> 6;
    float4 acc = make_float4(0.f, 0.f, 0.f, 0.f);
    #pragma unroll 4
    for (int s = 0; s < NCS; s++) {
        float ws = w[h][s];
        float4 xv = *reinterpret_cast<const float4*>(x + (size_t)(b * Lx + c * NCS + s) * ND + col);
        acc.x += ws * xv.x; acc.y += ws * xv.y; acc.z += ws * xv.z; acc.w += ws * xv.w;
    }
    *reinterpret_cast<float4*>(out + (size_t)(b * ncx + c) * ND + col) = acc;
}

// ---------------- row LayerNorm ----------------
__global__ void ln_kernel(const float* __restrict__ in, float* __restrict__ out,
                          const float* __restrict__ g, const float* __restrict__ be,
                          int rpb, int out_bstride, int out_off)
{
    __shared__ float red[32];
    const int r = blockIdx.x;
    const int tid = threadIdx.x;

    const float* x = in + (size_t)r * ND;
    float4 v = *reinterpret_cast<const float4*>(x + tid * 4);

    float s = v.x + v.y + v.z + v.w;
    #pragma unroll
    for (int o = 16; o; o >>= 1) s += __shfl_xor_sync(0xffffffffu, s, o);
    if ((tid & 31) == 0) red[tid >> 5] = s;
    __syncthreads();
    if (tid < 32) {
        float t = (tid < 8) ? red[tid] : 0.f;
        #pragma unroll
        for (int o = 4; o; o >>= 1) t += __shfl_xor_sync(0xffffffffu, t, o);
        if (tid == 0) red[0] = t;
    }
    __syncthreads();
    float mean = red[0] * (1.f / ND);
    __syncthreads();

    float d0 = v.x - mean, d1 = v.y - mean, d2 = v.z - mean, d3 = v.w - mean;
    float s2 = d0*d0 + d1*d1 + d2*d2 + d3*d3;
    #pragma unroll
    for (int o = 16; o; o >>= 1) s2 += __shfl_xor_sync(0xffffffffu, s2, o);
    if ((tid & 31) == 0) red[tid >> 5] = s2;
    __syncthreads();
    if (tid < 32) {
        float t = (tid < 8) ? red[tid] : 0.f;
        #pragma unroll
        for (int o = 4; o; o >>= 1) t += __shfl_xor_sync(0xffffffffu, t, o);
        if (tid == 0) red[0] = t;
    }
    __syncthreads();
    float rstd = rsqrtf(red[0] * (1.f / ND) + 1e-5f);

    const int orow = (r / rpb) * out_bstride + out_off + (r % rpb);
    const int c = tid * 4;
    float4 ov;
    ov.x = d0 * rstd * g[c + 0] + be[c + 0];
    ov.y = d1 * rstd * g[c + 1] + be[c + 1];
    ov.z = d2 * rstd * g[c + 2] + be[c + 2];
    ov.w = d3 * rstd * g[c + 3] + be[c + 3];
    *reinterpret_cast<float4*>(out + (size_t)orow * ND + c) = ov;
}

// ---------------- rel-shifted positional scores (tiled + f32x2) ----------------
// Piecewise mapping: f = 64+qc*128+c; q2_0 = f0/129; base0 = f0-129*q2_0; cstar = 129-base0
// c < cstar: q row = s (block q2_0), pc row = base0+c; else q row = 32+s, pc row = c-cstar.
// pc row 128 is a zero pad (c2 == 128 case).
#define PSTR 66
#define PCQ_SMEM_F (64*PSTR + 129*PSTR)
__global__ void __launch_bounds__(256) pcq_kernel(const float* __restrict__ q,
                                                  const float* __restrict__ posc,
                                                  float* __restrict__ pcq)
{
    extern __shared__ float sm[];
    float* qt = sm;                    // 64 x PSTR
    float* pc = sm + 64 * PSTR;       // 129 x PSTR

    const int blk = blockIdx.x;
    const int qc = blk & 63;
    const int h  = (blk >> 6) & 15;
    const int b  = blk >> 10;
    const int tid = threadIdx.x;
    const int wid = tid >> 5, lane = tid & 31;

    const int f0 = 64 + qc * 128;
    const int q2_0 = f0 / 129;
    const int base0 = f0 - 129 * q2_0;
    const int cstar = 129 - base0;

    // stage q rows q2_0*32 .. +63 (guard l < NL)
    for (int i = tid; i < 64 * 16; i += 256) {
        int r = i >> 4, c4 = (i & 15) << 2;
        int l = q2_0 * NCS + r;
        float4 v = make_float4(0.f, 0.f, 0.f, 0.f);
        if (l < NL) v = *reinterpret_cast<const float4*>(q + (size_t)(b * NL + l) * ND + h * NDH + c4);
        float* d = &qt[r * PSTR + c4];
        d[0] = v.x; d[1] = v.y; d[2] = v.z; d[3] = v.w;
    }
    // stage posc rows 0..127 + zero row 128
    for (int i = tid; i < 129 * 16; i += 256) {
        int r = i >> 4, c4 = (i & 15) << 2;
        float4 v = make_float4(0.f, 0.f, 0.f, 0.f);
        if (r < 128) v = *reinterpret_cast<const float4*>(posc + (size_t)r * ND + h * NDH + c4);
        float* d = &pc[r * PSTR + c4];
        d[0] = v.x; d[1] = v.y; d[2] = v.z; d[3] = v.w;
    }
    __syncthreads();

    const int s0 = wid * 4;
    int pcrow[4]; bool seg1[4];
    #pragma unroll
    for (int i = 0; i < 4; i++) {
        int c = lane + 32 * i;
        seg1[i] = (c >= cstar);
        pcrow[i] = seg1[i] ? (c - cstar) : (base0 + c);
    }

    ull acc[4][4];
    #pragma unroll
    for (int s = 0; s < 4; s++)
        #pragma unroll
        for (int i = 0; i < 4; i++) acc[s][i] = 0ull;

    for (int dp = 0; dp < 32; dp++) {
        ull q0[4], q1[4];
        #pragma unroll
        for (int s = 0; s < 4; s++) {
            q0[s] = *reinterpret_cast<const ull*>(&qt[(s0 + s) * PSTR + 2 * dp]);
            q1[s] = *reinterpret_cast<const ull*>(&qt[(32 + s0 + s) * PSTR + 2 * dp]);
        }
        #pragma unroll
        for (int i = 0; i < 4; i++) {
            ull pv = *reinterpret_cast<const ull*>(&pc[pcrow[i] * PSTR + 2 * dp]);
            ull p0 = seg1[i] ? 0ull : pv;
            ull p1 = seg1[i] ? pv : 0ull;
            #pragma unroll
            for (int s = 0; s < 4; s++) {
                fma2(acc[s][i], q0[s], p0);
                fma2(acc[s][i], q1[s], p1);
            }
        }
    }

    #pragma unroll
    for (int s = 0; s < 4; s++)
        #pragma unroll
        for (int i = 0; i < 4; i++)
            pcq[((size_t)(b * NH + h) * NL + qc * NCS + s0 + s) * NNC + lane + 32 * i] =
                fold2(acc[s][i]);
}

// ---------------- fused attention: scores + softmax + AV (tiled + f32x2) ----------------
#define ASTR 66
// smem floats: qs 2048 | sc 8192 | D 5120 | kb 160*66=10560 | rwb 64 | rrb 64
#define ATT_OFF_SC 2048
#define ATT_OFF_D  10240
#define ATT_OFF_KB 15360
#define ATT_OFF_RW 25920
#define ATT_OFF_RR 25984
#define ATT_SMEM_F 26048

__global__ void __launch_bounds__(256) attn_kernel(
    const float* __restrict__ q, const float* __restrict__ kcomp,
    const float* __restrict__ vcomp, const float* __restrict__ kwin,
    const float* __restrict__ vwin, const float* __restrict__ post,
    const float* __restrict__ pcq, const float* __restrict__ rwb,
    const float* __restrict__ rrb, float* __restrict__ outp)
{
    extern __shared__ float sm[];
    float* qs   = sm;
    float* sc   = sm + ATT_OFF_SC;
    float* Dm   = sm + ATT_OFF_D;
    float* kb   = sm + ATT_OFF_KB;
    float* rwbs = sm + ATT_OFF_RW;
    float* rrbs = sm + ATT_OFF_RR;

    const int tid = threadIdx.x;
    const int wid = tid >> 5, lane = tid & 31;
    const int blk = blockIdx.x;
    const int qc = blk & 63;
    const int h  = (blk >> 6) & 15;
    const int b  = blk >> 10;
    const int l0 = qc * NCS;
    const int s0 = wid * 4;

    // ---- load q rows + biases
    for (int i = tid; i < 32 * 16; i += 256) {
        int r = i >> 4, c4 = (i & 15) << 2;
        float4 v = *reinterpret_cast<const float4*>(q + (size_t)(b * NL + l0 + r) * ND + h * NDH + c4);
        *reinterpret_cast<float4*>(&qs[r * 64 + c4]) = v;
    }
    if (tid < 64) { rwbs[tid] = rwb[h * NDH + tid]; rrbs[tid] = rrb[h * NDH + tid]; }
    __syncthreads();

    // ---- Phase A: stage kcomp (128 rows), compute sc[:, 0:128] = q . kcomp
    for (int i = tid; i < 128 * 16; i += 256) {
        int r = i >> 4, c4 = (i & 15) << 2;
        float4 v = *reinterpret_cast<const float4*>(kcomp + (size_t)(b * NNC + r) * ND + h * NDH + c4);
        float* d = &kb[r * ASTR + c4];
        d[0] = v.x; d[1] = v.y; d[2] = v.z; d[3] = v.w;
    }
    __syncthreads();
    {
        ull acc[4][4];
        #pragma unroll
        for (int s = 0; s < 4; s++)
            #pragma unroll
            for (int i = 0; i < 4; i++) acc[s][i] = 0ull;
        for (int dp = 0; dp < 32; dp++) {
            ull qv[4];
            #pragma unroll
            for (int s = 0; s < 4; s++)
                qv[s] = *reinterpret_cast<const ull*>(&qs[(s0 + s) * 64 + 2 * dp]);
            #pragma unroll
            for (int i = 0; i < 4; i++) {
                ull kv = *reinterpret_cast<const ull*>(&kb[(lane + 32 * i) * ASTR + 2 * dp]);
                #pragma unroll
                for (int s = 0; s < 4; s++) fma2(acc[s][i], qv[s], kv);
            }
        }
        #pragma unroll
        for (int s = 0; s < 4; s++)
            #pragma unroll
            for (int i = 0; i < 4; i++)
                sc[(s0 + s) * 256 + lane + 32 * i] = fold2(acc[s][i]);
    }
    __syncthreads();

    // ---- Phase B: stage post (128 rows); also add pcq + mask to sc[:,0:128]
    for (int i = tid; i < 128 * 16; i += 256) {
        int r = i >> 4, c4 = (i & 15) << 2;
        float4 v = *reinterpret_cast<const float4*>(post + (size_t)r * ND + h * NDH + c4);
        float* d = &kb[r * ASTR + c4];
        d[0] = v.x; d[1] = v.y; d[2] = v.z; d[3] = v.w;
    }
    for (int i = tid; i < 32 * 128; i += 256) {
        int s_ = i >> 7, c = i & 127;
        float v = sc[s_ * 256 + c] + pcq[((size_t)(b * NH + h) * NL + l0 + s_) * NNC + c];
        if (c >= 64 && (c - 64) >= qc) v = -1e30f;
        sc[s_ * 256 + c] = v;
    }
    __syncthreads();
    // sc[:, 128:256] = (q + rrb) . post
    {
        ull acc[4][4];
        #pragma unroll
        for (int s = 0; s < 4; s++)
            #pragma unroll
            for (int i = 0; i < 4; i++) acc[s][i] = 0ull;
        for (int dp = 0; dp < 32; dp++) {
            ull rr = *reinterpret_cast<const ull*>(&rrbs[2 * dp]);
            ull qv[4];
            #pragma unroll
            for (int s = 0; s < 4; s++)
                qv[s] = add2(*reinterpret_cast<const ull*>(&qs[(s0 + s) * 64 + 2 * dp]), rr);
            #pragma unroll
            for (int i = 0; i < 4; i++) {
                ull kv = *reinterpret_cast<const ull*>(&kb[(lane + 32 * i) * ASTR + 2 * dp]);
                #pragma unroll
                for (int s = 0; s < 4; s++) fma2(acc[s][i], qv[s], kv);
            }
        }
        #pragma unroll
        for (int s = 0; s < 4; s++)
            #pragma unroll
            for (int i = 0; i < 4; i++)
                sc[(s0 + s) * 256 + 128 + lane + 32 * i] = fold2(acc[s][i]);
    }
    __syncthreads();

    // ---- Phase C: stage kwin band (160 rows), dense D = (q + rwb) . kband
    for (int i = tid; i < 160 * 16; i += 256) {
        int r = i >> 4, c4 = (i & 15) << 2;
        int idx = l0 + 1 + r;
        float4 v = make_float4(0.f, 0.f, 0.f, 0.f);
        if (idx < NWINROWS)
            v = *reinterpret_cast<const float4*>(kwin + (size_t)(b * NWINROWS + idx) * ND + h * NDH + c4);
        float* d = &kb[r * ASTR + c4];
        d[0] = v.x; d[1] = v.y; d[2] = v.z; d[3] = v.w;
    }
    __syncthreads();
    {
        ull acc[4][5];
        #pragma unroll
        for (int s = 0; s < 4; s++)
            #pragma unroll
            for (int i = 0; i < 5; i++) acc[s][i] = 0ull;
        for (int dp = 0; dp < 32; dp++) {
            ull rw = *reinterpret_cast<const ull*>(&rwbs[2 * dp]);
            ull qv[4];
            #pragma unroll
            for (int s = 0; s < 4; s++)
                qv[s] = add2(*reinterpret_cast<const ull*>(&qs[(s0 + s) * 64 + 2 * dp]), rw);
            #pragma unroll
            for (int i = 0; i < 5; i++) {
                ull kv = *reinterpret_cast<const ull*>(&kb[(lane + 32 * i) * ASTR + 2 * dp]);
                #pragma unroll
                for (int s = 0; s < 4; s++) fma2(acc[s][i], qv[s], kv);
            }
        }
        #pragma unroll
        for (int s = 0; s < 4; s++)
            #pragma unroll
            for (int i = 0; i < 5; i++)
                Dm[(s0 + s) * 160 + lane + 32 * i] = fold2(acc[s][i]);
    }
    __syncthreads();
    // gather band into window scores
    for (int i = tid; i < 32 * 128; i += 256) {
        int qi = i >> 7, j = i & 127;
        sc[qi * 256 + 128 + j] += Dm[qi * 160 + qi + j];
    }
    __syncthreads();

    // ---- softmax over 256 per row
    {
        const int w = tid >> 5, ln = tid & 31;
        for (int r = w; r < 32; r += 8) {
            float m = -1e30f;
            for (int c = ln; c < 256; c += 32) m = fmaxf(m, sc[r * 256 + c]);
            #pragma unroll
            for (int o = 16; o; o >>= 1) m = fmaxf(m, __shfl_xor_sync(0xffffffffu, m, o));
            float s = 0.f;
            for (int c = ln; c < 256; c += 32) {
                float e = __expf(sc[r * 256 + c] - m);
                sc[r * 256 + c] = e;
                s += e;
            }
            #pragma unroll
            for (int o = 16; o; o >>= 1) s += __shfl_xor_sync(0xffffffffu, s, o);
            float inv = 1.f / s;
            for (int c = ln; c < 256; c += 32) sc[r * 256 + c] *= inv;
        }
    }
    __syncthreads();

    // ---- Phase D: AV. acc per thread: 4 q-rows (s0..s0+3) x d-pair (2*lane)
    ull av[4] = {0ull, 0ull, 0ull, 0ull};
    // stage vcomp 128 rows
    for (int i = tid; i < 128 * 16; i += 256) {
        int r = i >> 4, c4 = (i & 15) << 2;
        float4 v = *reinterpret_cast<const float4*>(vcomp + (size_t)(b * NNC + r) * ND + h * NDH + c4);
        float* d = &kb[r * ASTR + c4];
        d[0] = v.x; d[1] = v.y; d[2] = v.z; d[3] = v.w;
    }
    __syncthreads();
    for (int c = 0; c < NNC; c++) {
        ull vv = *reinterpret_cast<const ull*>(&kb[c * ASTR + 2 * lane]);
        #pragma unroll
        for (int s = 0; s < 4; s++) {
            float sv = sc[(s0 + s) * 256 + c];
            fma2(av[s], pack2(sv), vv);
        }
    }
    __syncthreads();
    // stage vwin band 160 rows
    for (int i = tid; i < 160 * 16; i += 256) {
        int r = i >> 4, c4 = (i & 15) << 2;
        int idx = l0 + 1 + r;
        float4 v = make_float4(0.f, 0.f, 0.f, 0.f);
        if (idx < NWINROWS)
            v = *reinterpret_cast<const float4*>(vwin + (size_t)(b * NWINROWS + idx) * ND + h * NDH + c4);
        float* d = &kb[r * ASTR + c4];
        d[0] = v.x; d[1] = v.y; d[2] = v.z; d[3] = v.w;
    }
    __syncthreads();
    for (int r = 0; r < 160; r++) {
        ull vv = *reinterpret_cast<const ull*>(&kb[r * ASTR + 2 * lane]);
        #pragma unroll
        for (int s = 0; s < 4; s++) {
            int j = r - (s0 + s);
            if ((unsigned)j < 128u) {
                float sv = sc[(s0 + s) * 256 + 128 + j];
                fma2(av[s], pack2(sv), vv);
            }
        }
    }
    #pragma unroll
    for (int s = 0; s < 4; s++) {
        float2 o = unpack2(av[s]);
        *reinterpret_cast<float2*>(outp + (size_t)(b * NL + l0 + s0 + s) * ND + h * NDH + 2 * lane) = o;
    }
}

// ---------------- host launch ----------------
#define GETSYM(p, s) do { void* _t = nullptr; cudaGetSymbolAddress(&_t, s); (p) = decltype(p)(_t); } while (0)

static inline void tgemm(const __nv_bfloat16* Ahi, const __nv_bfloat16* Alo,
                         const __nv_bfloat16* Bhi, const __nv_bfloat16* Blo,
                         const float* bias, float* C, int M, int N, int K, float alpha)
{
    dim3 grid(N / 128, M / 128);
    tgemm_kernel<<<grid, 256, TG_SMEM_TOTAL>>>(Ahi, Alo, Bhi, Blo, bias, C, M, N, K, alpha);
}

extern "C" void kernel_launch(void* const* d_in, const int* in_sizes, int n_in,
                              void* d_out, int out_size)
{
    const float* h      = (const float*)d_in[0];
    const float* hcache = (const float*)d_in[1];
    const float* key_pe = (const float*)d_in[2];
    const float* poswin = (const float*)d_in[3];
    const float* Wq  = (const float*)d_in[4];
    const float* Wk  = (const float*)d_in[5];
    const float* Wv  = (const float*)d_in[6];
    const float* Wo  = (const float*)d_in[7];
    const float* Wd  = (const float*)d_in[8];
    const float* bd  = (const float*)d_in[9];
    const float* Wr  = (const float*)d_in[10];
    const float* br  = (const float*)d_in[11];
    const float* Wrc = (const float*)d_in[12];
    const float* brc = (const float*)d_in[13];
    const float* rrb = (const float*)d_in[14];
    const float* rwb = (const float*)d_in[15];
    const float* g_dp = (const float*)d_in[16];
    const float* b_dp = (const float*)d_in[17];
    const float* g_w  = (const float*)d_in[18];
    const float* b_w  = (const float*)d_in[19];
    float* outp = (float*)d_out;

    float *q, *kbp, *vbp, *sh, *shc, *sch, *schc, *hcm, *compk, *compv;
    float *hcmk, *hcmv, *kcomp, *vcomp, *hwk, *hwv, *kwin, *vwin, *post, *posc, *pcq, *attn;
    GETSYM(q, g_q); GETSYM(kbp, g_kbp); GETSYM(vbp, g_vbp);
    GETSYM(sh, g_sh); GETSYM(shc, g_shc); GETSYM(sch, g_sch); GETSYM(schc, g_schc);
    GETSYM(hcm, g_hcm); GETSYM(compk, g_compk); GETSYM(compv, g_compv);
    GETSYM(hcmk, g_hcmk); GETSYM(hcmv, g_hcmv);
    GETSYM(kcomp, g_kcomp); GETSYM(vcomp, g_vcomp);
    GETSYM(hwk, g_hwk); GETSYM(hwv, g_hwv);
    GETSYM(kwin, g_kwin); GETSYM(vwin, g_vwin);
    GETSYM(post, g_post); GETSYM(posc, g_posc);
    GETSYM(pcq, g_pcq); GETSYM(attn, g_attn);

    __nv_bfloat16 *ahi, *alo, *xhi, *xlo;
    __nv_bfloat16 *wqh, *wql, *wkh, *wkl, *wvh, *wvl, *woh, *wol, *wrh, *wrl, *wrch, *wrcl;
    GETSYM(ahi, g_ahi); GETSYM(alo, g_alo); GETSYM(xhi, g_xhi); GETSYM(xlo, g_xlo);
    GETSYM(wqh, g_wqh); GETSYM(wql, g_wql); GETSYM(wkh, g_wkh); GETSYM(wkl, g_wkl);
    GETSYM(wvh, g_wvh); GETSYM(wvl, g_wvl); GETSYM(woh, g_woh); GETSYM(wol, g_wol);
    GETSYM(wrh, g_wrh); GETSYM(wrl, g_wrl); GETSYM(wrch, g_wrch); GETSYM(wrcl, g_wrcl);

    const int ATTN_SMEM = ATT_SMEM_F * (int)sizeof(float);
    const int PCQ_SMEM  = PCQ_SMEM_F * (int)sizeof(float);
    cudaFuncSetAttribute(attn_kernel, cudaFuncAttributeMaxDynamicSharedMemorySize, ATTN_SMEM);
    cudaFuncSetAttribute(pcq_kernel,  cudaFuncAttributeMaxDynamicSharedMemorySize, PCQ_SMEM);
    cudaFuncSetAttribute(tgemm_kernel, cudaFuncAttributeMaxDynamicSharedMemorySize, TG_SMEM_TOTAL);

    const int M = NB * NL;   // 8192

    // 0. weight transpose+split, activation split
    dim3 wg(32, 32);
    wsplit_kernel<<<wg, 256>>>(Wq,  wqh,  wql);
    wsplit_kernel<<<wg, 256>>>(Wk,  wkh,  wkl);
    wsplit_kernel<<<wg, 256>>>(Wv,  wvh,  wvl);
    wsplit_kernel<<<wg, 256>>>(Wo,  woh,  wol);
    wsplit_kernel<<<wg, 256>>>(Wr,  wrh,  wrl);
    wsplit_kernel<<<wg, 256>>>(Wrc, wrch, wrcl);
    split_kernel<<<M, 256>>>(h, ahi, alo, M, 0, 0);

    // 1. projections of h (q pre-scaled by 1/sqrt(DH) = 0.125)
    tgemm(ahi, alo, wqh, wql, nullptr, q,   M, ND, ND, 0.125f);
    tgemm(ahi, alo, wkh, wkl, nullptr, kbp, M, ND, ND, 1.f);
    tgemm(ahi, alo, wvh, wvl, nullptr, vbp, M, ND, ND, 1.f);

    // 2. chunk scores of h and h_cache (N=16 GEMV)
    gemv16_kernel<<<M / 64, 256>>>(h,      Wd, bd, sh);
    gemv16_kernel<<<M / 64, 256>>>(hcache, Wd, bd, shc);
    chunk_softmax_kernel<<<NB * NNQ, 512>>>(sh,  sch,  NL);
    chunk_softmax_kernel<<<NB * NNQ, 512>>>(shc, schc, NCACHE);

    // 3. compress h_cache, k_bp, v_bp
    compress_kernel<<<NB * NNQ, 256>>>(hcache, schc, hcm,   NCACHE);
    compress_kernel<<<NB * NNQ, 256>>>(kbp,    sch,  compk, NL);
    compress_kernel<<<NB * NNQ, 256>>>(vbp,    sch,  compv, NL);

    // 4. cache-side K/V projections + LN into kcomp/vcomp rows [0,64)
    split_kernel<<<NB * NNQ, 256>>>(hcm, xhi, xlo, NB * NNQ, 0, 0);
    tgemm(xhi, xlo, wkh, wkl, nullptr, hcmk, NB * NNQ, ND, ND, 1.f);
    tgemm(xhi, xlo, wvh, wvl, nullptr, hcmv, NB * NNQ, ND, ND, 1.f);
    ln_kernel<<<NB * NNQ, 256>>>(hcmk,  kcomp, g_dp, b_dp, NNQ, NNC, 0);
    ln_kernel<<<NB * NNQ, 256>>>(hcmv,  vcomp, g_dp, b_dp, NNQ, NNC, 0);
    ln_kernel<<<NB * NNQ, 256>>>(compk, kcomp, g_dp, b_dp, NNQ, NNC, 64);
    ln_kernel<<<NB * NNQ, 256>>>(compv, vcomp, g_dp, b_dp, NNQ, NNC, 64);

    // 5. window K/V
    split_kernel<<<NB * NW, 256>>>(hcache, xhi, xlo, NW, NCACHE, NCACHE - NW);
    tgemm(xhi, xlo, wkh, wkl, nullptr, hwk, NB * NW, ND, ND, 1.f);
    tgemm(xhi, xlo, wvh, wvl, nullptr, hwv, NB * NW, ND, ND, 1.f);
    ln_kernel<<<NB * NW, 256>>>(hwk, kwin, g_w, b_w, NW, NWINROWS, 0);
    ln_kernel<<<NB * NW, 256>>>(hwv, vwin, g_w, b_w, NW, NWINROWS, 0);
    ln_kernel<<<M, 256>>>(kbp, kwin, g_w, b_w, NL, NWINROWS, NW);
    ln_kernel<<<M, 256>>>(vbp, vwin, g_w, b_w, NL, NWINROWS, NW);

    // 6. positional projections
    split_kernel<<<NW, 256>>>(poswin, xhi, xlo, NW, 0, 0);
    tgemm(xhi, xlo, wrh, wrl, br, post, NW, ND, ND, 1.f);
    split_kernel<<<NNC, 256>>>(key_pe, xhi, xlo, NNC, 0, 0);
    tgemm(xhi, xlo, wrch, wrcl, brc, posc, NNC, ND, ND, 1.f);

    // 7. rel-shifted positional scores
    pcq_kernel<<<NB * NH * NNQ, 256, PCQ_SMEM>>>(q, posc, pcq);

    // 8. fused attention
    attn_kernel<<<NB * NH * NNQ, 256, ATTN_SMEM>>>(q, kcomp, vcomp, kwin, vwin,
                                                   post, pcq, rwb, rrb, attn);

    // 9. output projection
    split_kernel<<<M, 256>>>(attn, ahi, alo, M, 0, 0);
    tgemm(ahi, alo, woh, wol, nullptr, outp, M, ND, ND, 1.f);
}